// round 1
// baseline (speedup 1.0000x reference)
#include <cuda_runtime.h>

// Problem constants
#define BATCHN 2
#define SEQ    1024
#define DMODEL 1024
#define NHEAD  8
#define DVDIM  128

// Scratch (allocation-free rule: __device__ globals)
__device__ float g_q[BATCHN * SEQ * DMODEL];   // (2048, 1024)
__device__ float g_k[BATCHN * SEQ * DVDIM];    // (2048, 128)
__device__ float g_v[BATCHN * SEQ * DVDIM];    // (2048, 128)
__device__ float g_o[BATCHN * SEQ * DMODEL];   // (2048, 1024) attention out (pre-Wo)

// round-to-nearest tf32 (halves error vs HW truncation)
__device__ __forceinline__ float tf32r(float x) {
    asm("cvt.rna.tf32.f32 %0, %0;" : "+f"(x));
    return x;
}

__device__ __forceinline__ void mma_tf32(float c[4], const unsigned a[4], const unsigned b[2]) {
    asm volatile(
        "mma.sync.aligned.m16n8k8.row.col.f32.tf32.tf32.f32 "
        "{%0,%1,%2,%3}, {%4,%5,%6,%7}, {%8,%9}, {%0,%1,%2,%3};\n"
        : "+f"(c[0]), "+f"(c[1]), "+f"(c[2]), "+f"(c[3])
        : "r"(a[0]), "r"(a[1]), "r"(a[2]), "r"(a[3]), "r"(b[0]), "r"(b[1]));
}

// ---------------------------------------------------------------------------
// Generic tf32 GEMM: C(M,N) = A(M,K) @ B(K,N) + bias(N).  A,B,C row-major.
// BM=128 BN=128 BK=32, 256 threads, warp tile 32x64 (4x2 warps), 8x8 reg tile.
// Requires M%128==0, N%128==0, K%32==0 (true for all our shapes).
// ---------------------------------------------------------------------------
__global__ __launch_bounds__(256, 1)
void gemm_tf32(const float* __restrict__ A, const float* __restrict__ Bm,
               const float* __restrict__ bias, float* __restrict__ C,
               int M, int N, int K)
{
    __shared__ float As[128][36];   // stride 36: a-frag lds conflict-free (4r+c)
    __shared__ float Bs[32][136];   // stride 136: b-frag lds conflict-free (8k+n)

    const int tid  = threadIdx.x;
    const int lane = tid & 31;
    const int w    = tid >> 5;
    const int la3  = lane & 3;
    const int lg4  = lane >> 2;
    const int wm   = (w & 3) * 32;   // warp m offset within CTA tile
    const int wn   = (w >> 2) * 64;  // warp n offset
    const int bm   = blockIdx.y * 128;
    const int bn   = blockIdx.x * 128;

    float c[2][8][4];
#pragma unroll
    for (int mt = 0; mt < 2; mt++)
#pragma unroll
        for (int nt = 0; nt < 8; nt++)
#pragma unroll
            for (int i = 0; i < 4; i++) c[mt][nt][i] = 0.f;

    for (int kb = 0; kb < K; kb += 32) {
        // Load A tile 128x32 (4 float4 per thread)
#pragma unroll
        for (int i = 0; i < 4; i++) {
            int vid = tid + i * 256;          // 0..1023 float4 slots
            int r = vid >> 3;                 // 8 float4 per row
            int cc = (vid & 7) * 4;
            float4 f = *reinterpret_cast<const float4*>(&A[(size_t)(bm + r) * K + kb + cc]);
            As[r][cc + 0] = tf32r(f.x);
            As[r][cc + 1] = tf32r(f.y);
            As[r][cc + 2] = tf32r(f.z);
            As[r][cc + 3] = tf32r(f.w);
        }
        // Load B tile 32x128
#pragma unroll
        for (int i = 0; i < 4; i++) {
            int vid = tid + i * 256;
            int r = vid >> 5;                 // 32 float4 per row
            int cc = (vid & 31) * 4;
            float4 f = *reinterpret_cast<const float4*>(&Bm[(size_t)(kb + r) * N + bn + cc]);
            Bs[r][cc + 0] = tf32r(f.x);
            Bs[r][cc + 1] = tf32r(f.y);
            Bs[r][cc + 2] = tf32r(f.z);
            Bs[r][cc + 3] = tf32r(f.w);
        }
        __syncthreads();

#pragma unroll
        for (int kk = 0; kk < 4; kk++) {
            const int k0 = kk * 8;
            unsigned a[2][4];
#pragma unroll
            for (int mt = 0; mt < 2; mt++) {
                int r = wm + mt * 16 + lg4;
                a[mt][0] = __float_as_uint(As[r][k0 + la3]);
                a[mt][1] = __float_as_uint(As[r + 8][k0 + la3]);
                a[mt][2] = __float_as_uint(As[r][k0 + la3 + 4]);
                a[mt][3] = __float_as_uint(As[r + 8][k0 + la3 + 4]);
            }
            unsigned b[8][2];
#pragma unroll
            for (int nt = 0; nt < 8; nt++) {
                int cn = wn + nt * 8 + lg4;
                b[nt][0] = __float_as_uint(Bs[k0 + la3][cn]);
                b[nt][1] = __float_as_uint(Bs[k0 + la3 + 4][cn]);
            }
#pragma unroll
            for (int mt = 0; mt < 2; mt++)
#pragma unroll
                for (int nt = 0; nt < 8; nt++)
                    mma_tf32(c[mt][nt], a[mt], b[nt]);
        }
        __syncthreads();
    }

    // Epilogue: + bias, store fp32
#pragma unroll
    for (int mt = 0; mt < 2; mt++) {
#pragma unroll
        for (int nt = 0; nt < 8; nt++) {
            int r0 = bm + wm + mt * 16 + lg4;
            int cn = bn + wn + nt * 8 + la3 * 2;
            float b0 = bias[cn], b1 = bias[cn + 1];
            C[(size_t)r0 * N + cn]           = c[mt][nt][0] + b0;
            C[(size_t)r0 * N + cn + 1]       = c[mt][nt][1] + b1;
            C[(size_t)(r0 + 8) * N + cn]     = c[mt][nt][2] + b0;
            C[(size_t)(r0 + 8) * N + cn + 1] = c[mt][nt][3] + b1;
        }
    }
}

// ---------------------------------------------------------------------------
// Fused flash attention (per CTA: one (b,h) pair, 128-query tile, 1024 keys).
// Q_h is the contiguous block q[b, h*128:(h+1)*128, :] viewed as (1024,128).
// The reference's 8x key-tiling cancels in softmax -> plain 1024-key attention.
// 256 threads (8 warps); warp w owns query rows [w*16, w*16+16), full key/dv
// range -> softmax reductions are intra-quad shuffles only.
// smem: Qs(128x132) Ks(128x132, reused as P) Vs(128x136) = 200 KB dynamic.
// ---------------------------------------------------------------------------
__global__ __launch_bounds__(256, 1)
void attn_kernel(const float* __restrict__ q, const float* __restrict__ k,
                 const float* __restrict__ v, float* __restrict__ o)
{
    extern __shared__ float sm[];
    float (*Qs)[132] = reinterpret_cast<float(*)[132]>(sm);
    float (*Ks)[132] = reinterpret_cast<float(*)[132]>(sm + 128 * 132);        // also P
    float (*Vs)[136] = reinterpret_cast<float(*)[136]>(sm + 2 * 128 * 132);

    const int tid  = threadIdx.x;
    const int lane = tid & 31;
    const int w    = tid >> 5;
    const int la3  = lane & 3;
    const int lg4  = lane >> 2;
    const int qr   = w * 16 + lg4;          // this thread's first query row (of 2)

    const int bh = blockIdx.x;              // 0..15
    const int qt = blockIdx.y;              // 0..7
    const int b  = bh >> 3;
    const int h  = bh & 7;

    const float scale = 0.088388347648318447f;   // 1/sqrt(128)

    const float* Qg = q + (size_t)b * SEQ * DMODEL + (size_t)h * 128 * DMODEL + (size_t)qt * 128 * DVDIM;
    const float* Kg = k + (size_t)b * SEQ * DVDIM;
    const float* Vg = v + (size_t)b * SEQ * DVDIM;
    float*       Og = o + (size_t)b * SEQ * DMODEL + (size_t)h * 128 * DMODEL + (size_t)qt * 128 * DVDIM;

    // Load Q tile (pre-scaled, tf32-rounded)
#pragma unroll
    for (int i = 0; i < 16; i++) {
        int vid = tid + i * 256;          // 0..4095 float4 slots
        int r = vid >> 5;
        int cc = (vid & 31) * 4;
        float4 f = *reinterpret_cast<const float4*>(&Qg[(size_t)r * 128 + cc]);
        Qs[r][cc + 0] = tf32r(f.x * scale);
        Qs[r][cc + 1] = tf32r(f.y * scale);
        Qs[r][cc + 2] = tf32r(f.z * scale);
        Qs[r][cc + 3] = tf32r(f.w * scale);
    }

    float oacc[16][4];
#pragma unroll
    for (int nt = 0; nt < 16; nt++)
#pragma unroll
        for (int i = 0; i < 4; i++) oacc[nt][i] = 0.f;
    float m0 = -1e30f, m1 = -1e30f, l0 = 0.f, l1 = 0.f;

    for (int j = 0; j < 8; j++) {
        __syncthreads();   // prior iter's P/V reads done (and Q visible on j==0)
        // Load K, V tiles (128x128 each)
#pragma unroll
        for (int i = 0; i < 16; i++) {
            int vid = tid + i * 256;
            int r = vid >> 5;
            int cc = (vid & 31) * 4;
            float4 fk = *reinterpret_cast<const float4*>(&Kg[(size_t)(j * 128 + r) * 128 + cc]);
            Ks[r][cc + 0] = tf32r(fk.x);
            Ks[r][cc + 1] = tf32r(fk.y);
            Ks[r][cc + 2] = tf32r(fk.z);
            Ks[r][cc + 3] = tf32r(fk.w);
            float4 fv = *reinterpret_cast<const float4*>(&Vg[(size_t)(j * 128 + r) * 128 + cc]);
            Vs[r][cc + 0] = tf32r(fv.x);
            Vs[r][cc + 1] = tf32r(fv.y);
            Vs[r][cc + 2] = tf32r(fv.z);
            Vs[r][cc + 3] = tf32r(fv.w);
        }
        __syncthreads();

        // GEMM1: S(16 x 128) = Qtile(16 x 128) @ K_j^T
        float s[16][4];
#pragma unroll
        for (int nt = 0; nt < 16; nt++)
#pragma unroll
            for (int i = 0; i < 4; i++) s[nt][i] = 0.f;

#pragma unroll
        for (int kk = 0; kk < 16; kk++) {
            const int k0 = kk * 8;
            unsigned a[4];
            a[0] = __float_as_uint(Qs[qr][k0 + la3]);
            a[1] = __float_as_uint(Qs[qr + 8][k0 + la3]);
            a[2] = __float_as_uint(Qs[qr][k0 + la3 + 4]);
            a[3] = __float_as_uint(Qs[qr + 8][k0 + la3 + 4]);
#pragma unroll
            for (int nt = 0; nt < 16; nt++) {
                unsigned bb[2];
                bb[0] = __float_as_uint(Ks[nt * 8 + lg4][k0 + la3]);
                bb[1] = __float_as_uint(Ks[nt * 8 + lg4][k0 + la3 + 4]);
                mma_tf32(s[nt], a, bb);
            }
        }

        // Online softmax update (rows qr and qr+8; quad-local reductions)
        float rm0 = -1e30f, rm1 = -1e30f;
#pragma unroll
        for (int nt = 0; nt < 16; nt++) {
            rm0 = fmaxf(rm0, fmaxf(s[nt][0], s[nt][1]));
            rm1 = fmaxf(rm1, fmaxf(s[nt][2], s[nt][3]));
        }
        rm0 = fmaxf(rm0, __shfl_xor_sync(0xffffffffu, rm0, 1));
        rm0 = fmaxf(rm0, __shfl_xor_sync(0xffffffffu, rm0, 2));
        rm1 = fmaxf(rm1, __shfl_xor_sync(0xffffffffu, rm1, 1));
        rm1 = fmaxf(rm1, __shfl_xor_sync(0xffffffffu, rm1, 2));

        float mn0 = fmaxf(m0, rm0), mn1 = fmaxf(m1, rm1);
        float al0 = __expf(m0 - mn0), al1 = __expf(m1 - mn1);
        float rs0 = 0.f, rs1 = 0.f;
#pragma unroll
        for (int nt = 0; nt < 16; nt++) {
            s[nt][0] = __expf(s[nt][0] - mn0);
            s[nt][1] = __expf(s[nt][1] - mn0);
            s[nt][2] = __expf(s[nt][2] - mn1);
            s[nt][3] = __expf(s[nt][3] - mn1);
            rs0 += s[nt][0] + s[nt][1];
            rs1 += s[nt][2] + s[nt][3];
        }
        rs0 += __shfl_xor_sync(0xffffffffu, rs0, 1);
        rs0 += __shfl_xor_sync(0xffffffffu, rs0, 2);
        rs1 += __shfl_xor_sync(0xffffffffu, rs1, 1);
        rs1 += __shfl_xor_sync(0xffffffffu, rs1, 2);

        l0 = l0 * al0 + rs0;
        l1 = l1 * al1 + rs1;
        m0 = mn0;
        m1 = mn1;
#pragma unroll
        for (int nt = 0; nt < 16; nt++) {
            oacc[nt][0] *= al0;
            oacc[nt][1] *= al0;
            oacc[nt][2] *= al1;
            oacc[nt][3] *= al1;
        }

        __syncthreads();   // all warps done reading Ks (GEMM1)
        // Write P into Ks buffer (tf32-rounded; becomes mma A operand)
#pragma unroll
        for (int nt = 0; nt < 16; nt++) {
            int pc = nt * 8 + la3 * 2;
            Ks[qr][pc]         = tf32r(s[nt][0]);
            Ks[qr][pc + 1]     = tf32r(s[nt][1]);
            Ks[qr + 8][pc]     = tf32r(s[nt][2]);
            Ks[qr + 8][pc + 1] = tf32r(s[nt][3]);
        }
        __syncthreads();

        // GEMM2: O(16 x 128) += P(16 x 128) @ V(128 x 128)
#pragma unroll
        for (int kk = 0; kk < 16; kk++) {
            const int k0 = kk * 8;
            unsigned a[4];
            a[0] = __float_as_uint(Ks[qr][k0 + la3]);
            a[1] = __float_as_uint(Ks[qr + 8][k0 + la3]);
            a[2] = __float_as_uint(Ks[qr][k0 + la3 + 4]);
            a[3] = __float_as_uint(Ks[qr + 8][k0 + la3 + 4]);
#pragma unroll
            for (int nt = 0; nt < 16; nt++) {
                unsigned bb[2];
                bb[0] = __float_as_uint(Vs[k0 + la3][nt * 8 + lg4]);
                bb[1] = __float_as_uint(Vs[k0 + la3 + 4][nt * 8 + lg4]);
                mma_tf32(oacc[nt], a, bb);
            }
        }
    }

    // Finalize: divide by softmax denom, write out
    float inv0 = 1.f / l0, inv1 = 1.f / l1;
#pragma unroll
    for (int nt = 0; nt < 16; nt++) {
        int cc = nt * 8 + la3 * 2;
        Og[(size_t)qr * 128 + cc]           = oacc[nt][0] * inv0;
        Og[(size_t)qr * 128 + cc + 1]       = oacc[nt][1] * inv0;
        Og[(size_t)(qr + 8) * 128 + cc]     = oacc[nt][2] * inv1;
        Og[(size_t)(qr + 8) * 128 + cc + 1] = oacc[nt][3] * inv1;
    }
}

// ---------------------------------------------------------------------------
extern "C" void kernel_launch(void* const* d_in, const int* in_sizes, int n_in,
                              void* d_out, int out_size)
{
    const float* x  = (const float*)d_in[0];
    const float* Wq = (const float*)d_in[1];
    const float* bq = (const float*)d_in[2];
    const float* Wk = (const float*)d_in[3];
    const float* bk = (const float*)d_in[4];
    const float* Wv = (const float*)d_in[5];
    const float* bv = (const float*)d_in[6];
    const float* Wo = (const float*)d_in[7];
    const float* bo = (const float*)d_in[8];
    float* out = (float*)d_out;

    float *pq, *pk, *pv, *po;
    cudaGetSymbolAddress((void**)&pq, g_q);
    cudaGetSymbolAddress((void**)&pk, g_k);
    cudaGetSymbolAddress((void**)&pv, g_v);
    cudaGetSymbolAddress((void**)&po, g_o);

    const int ATTN_SMEM = (2 * 128 * 132 + 128 * 136) * 4;   // 204800 B
    cudaFuncSetAttribute(attn_kernel, cudaFuncAttributeMaxDynamicSharedMemorySize, ATTN_SMEM);

    const int M = BATCHN * SEQ;   // 2048
    dim3 blk(256);

    // Projections
    gemm_tf32<<<dim3(DMODEL / 128, M / 128), blk>>>(x, Wq, bq, pq, M, DMODEL, DMODEL);
    gemm_tf32<<<dim3(DVDIM / 128, M / 128), blk>>>(x, Wk, bk, pk, M, DVDIM, DMODEL);
    gemm_tf32<<<dim3(DVDIM / 128, M / 128), blk>>>(x, Wv, bv, pv, M, DVDIM, DMODEL);

    // Attention: 16 (b,h) pairs x 8 query tiles
    attn_kernel<<<dim3(16, 8), blk, ATTN_SMEM>>>(pq, pk, pv, po);

    // Output projection
    gemm_tf32<<<dim3(DMODEL / 128, M / 128), blk>>>(po, Wo, bo, out, M, DMODEL, DMODEL);
}

// round 3
// speedup vs baseline: 1.3807x; 1.3807x over previous
#include <cuda_runtime.h>

#define SEQ    1024
#define DMODEL 1024
#define DV     128

// ------------------------- scratch (__device__ globals) ---------------------
__device__ float g_xr [2 * SEQ * DMODEL];     // tf32-rounded x
__device__ float g_wqr[DMODEL * DMODEL];
__device__ float g_wkr[DMODEL * DV];
__device__ float g_wvr[DMODEL * DV];
__device__ float g_wor[DMODEL * DMODEL];
__device__ float g_q  [2 * SEQ * DMODEL];
__device__ float g_k  [2 * SEQ * DV];
__device__ float g_v  [2 * SEQ * DV];
__device__ float g_o  [2 * SEQ * DMODEL];

// round-to-nearest tf32
__device__ __forceinline__ float tf32r(float x) {
    asm("cvt.rna.tf32.f32 %0, %0;" : "+f"(x));
    return x;
}

__device__ __forceinline__ void mma_tf32(float c[4], const unsigned a[4], const unsigned b[2]) {
    asm volatile(
        "mma.sync.aligned.m16n8k8.row.col.f32.tf32.tf32.f32 "
        "{%0,%1,%2,%3}, {%4,%5,%6,%7}, {%8,%9}, {%0,%1,%2,%3};\n"
        : "+f"(c[0]), "+f"(c[1]), "+f"(c[2]), "+f"(c[3])
        : "r"(a[0]), "r"(a[1]), "r"(a[2]), "r"(a[3]), "r"(b[0]), "r"(b[1]));
}

// ------------------------- prepass: round inputs to tf32 --------------------
__global__ void round_pre(const float* __restrict__ x,  const float* __restrict__ wq,
                          const float* __restrict__ wk, const float* __restrict__ wv,
                          const float* __restrict__ wo)
{
    const size_t E0 = 524288;            // x      float4 count
    const size_t E1 = E0 + 262144;       // wq
    const size_t E2 = E1 + 32768;        // wk
    const size_t E3 = E2 + 32768;        // wv
    const size_t E4 = E3 + 262144;       // wo
    size_t i = (size_t)blockIdx.x * blockDim.x + threadIdx.x;
    size_t stride = (size_t)gridDim.x * blockDim.x;
    for (; i < E4; i += stride) {
        const float4* s; float4* d; size_t off;
        if      (i < E0) { s = (const float4*)x;  d = (float4*)g_xr;  off = i;      }
        else if (i < E1) { s = (const float4*)wq; d = (float4*)g_wqr; off = i - E0; }
        else if (i < E2) { s = (const float4*)wk; d = (float4*)g_wkr; off = i - E1; }
        else if (i < E3) { s = (const float4*)wv; d = (float4*)g_wvr; off = i - E2; }
        else             { s = (const float4*)wo; d = (float4*)g_wor; off = i - E3; }
        float4 f = s[off];
        f.x = tf32r(f.x); f.y = tf32r(f.y); f.z = tf32r(f.z); f.w = tf32r(f.w);
        d[off] = f;
    }
}

// ------------------------- GEMM core (BM=128 BN=128 BK=32) ------------------
// 128 threads / 4 warps, warp tile 64x64 (8 MAC per smem byte -> crossbar-balanced),
// cp.async 2-stage double buffer. K fixed at 1024. A,B pre-rounded to tf32.
// smem: As[2][128][36] + Bs[2][32][136] = 71680 B.

__device__ __forceinline__ void cpa16(float* dst, const float* src) {
    unsigned d = (unsigned)__cvta_generic_to_shared(dst);
    asm volatile("cp.async.cg.shared.global [%0], [%1], 16;\n" :: "r"(d), "l"(src) : "memory");
}

__device__ __forceinline__ void gemm_load_tiles(float* sm, int s,
                                                const float* __restrict__ A,
                                                const float* __restrict__ Bm,
                                                int N, int bm, int bn, int kb, int tid)
{
    float* As = sm + s * (128 * 36);
    float* Bs = sm + 2 * 128 * 36 + s * (32 * 136);
#pragma unroll
    for (int i = 0; i < 8; i++) {                 // A: 128x32 -> 1024 16B chunks
        int id = tid + i * 128;
        int r = id >> 3, c4 = (id & 7) * 4;
        cpa16(As + r * 36 + c4, A + (size_t)(bm + r) * 1024 + kb + c4);
    }
#pragma unroll
    for (int i = 0; i < 8; i++) {                 // B: 32x128
        int id = tid + i * 128;
        int r = id >> 5, c4 = (id & 31) * 4;
        cpa16(Bs + r * 136 + c4, Bm + (size_t)(kb + r) * N + bn + c4);
    }
    asm volatile("cp.async.commit_group;\n" ::: "memory");
}

__device__ __forceinline__ void gemm_core(const float* __restrict__ A,
                                          const float* __restrict__ Bm,
                                          const float* __restrict__ bias,
                                          float* __restrict__ C,
                                          int N, int Nc, int bm, int bn, int bnc,
                                          float* sm)
{
    const int tid  = threadIdx.x;
    const int lane = tid & 31;
    const int w    = tid >> 5;
    const int la3  = lane & 3;
    const int lg4  = lane >> 2;
    const int wm   = (w & 1) * 64;
    const int wn   = (w >> 1) * 64;

    float c[4][8][4];
#pragma unroll
    for (int mt = 0; mt < 4; mt++)
#pragma unroll
        for (int nt = 0; nt < 8; nt++)
#pragma unroll
            for (int i = 0; i < 4; i++) c[mt][nt][i] = 0.f;

    gemm_load_tiles(sm, 0, A, Bm, N, bm, bn, 0, tid);

    for (int kbi = 0; kbi < 32; kbi++) {
        const int s = kbi & 1;
        asm volatile("cp.async.wait_group 0;\n" ::: "memory");
        __syncthreads();                           // stage s ready; all warps past stage s^1
        if (kbi < 31)
            gemm_load_tiles(sm, s ^ 1, A, Bm, N, bm, bn, (kbi + 1) * 32, tid);

        float (*As)[36]  = (float(*)[36])(sm + s * (128 * 36));
        float (*Bs)[136] = (float(*)[136])(sm + 2 * 128 * 36 + s * (32 * 136));
#pragma unroll
        for (int kk = 0; kk < 4; kk++) {
            const int k0 = kk * 8;
            unsigned a[4][4];
#pragma unroll
            for (int mt = 0; mt < 4; mt++) {
                int r = wm + mt * 16 + lg4;
                a[mt][0] = __float_as_uint(As[r][k0 + la3]);
                a[mt][1] = __float_as_uint(As[r + 8][k0 + la3]);
                a[mt][2] = __float_as_uint(As[r][k0 + la3 + 4]);
                a[mt][3] = __float_as_uint(As[r + 8][k0 + la3 + 4]);
            }
            unsigned b[8][2];
#pragma unroll
            for (int nt = 0; nt < 8; nt++) {
                int cn = wn + nt * 8 + lg4;
                b[nt][0] = __float_as_uint(Bs[k0 + la3][cn]);
                b[nt][1] = __float_as_uint(Bs[k0 + la3 + 4][cn]);
            }
#pragma unroll
            for (int mt = 0; mt < 4; mt++)
#pragma unroll
                for (int nt = 0; nt < 8; nt++)
                    mma_tf32(c[mt][nt], a[mt], b[nt]);
        }
    }

    // epilogue: +bias, fp32 store
#pragma unroll
    for (int mt = 0; mt < 4; mt++) {
#pragma unroll
        for (int nt = 0; nt < 8; nt++) {
            int row = bm + wm + mt * 16 + lg4;
            int cn  = wn + nt * 8 + la3 * 2;
            float b0 = bias[bn + cn], b1 = bias[bn + cn + 1];
            float2 v0 = make_float2(c[mt][nt][0] + b0, c[mt][nt][1] + b1);
            float2 v1 = make_float2(c[mt][nt][2] + b0, c[mt][nt][3] + b1);
            *(float2*)&C[(size_t)row * Nc + bnc + cn]       = v0;
            *(float2*)&C[(size_t)(row + 8) * Nc + bnc + cn] = v1;
        }
    }
}

// Fused QKV projection: grid (10, 16). bx<8 -> Q col-block, bx==8 -> K, bx==9 -> V.
__global__ __launch_bounds__(128)
void qkv_kernel(const float* __restrict__ bq, const float* __restrict__ bk,
                const float* __restrict__ bv)
{
    extern __shared__ float sm[];
    const int bx = blockIdx.x;
    const int bm = blockIdx.y * 128;
    if (bx < 8)
        gemm_core(g_xr, g_wqr, bq, g_q, 1024, 1024, bm, bx * 128, bx * 128, sm);
    else if (bx == 8)
        gemm_core(g_xr, g_wkr, bk, g_k, 128, 128, bm, 0, 0, sm);
    else
        gemm_core(g_xr, g_wvr, bv, g_v, 128, 128, bm, 0, 0, sm);
}

// Output projection: grid (8, 16).
__global__ __launch_bounds__(128)
void wo_kernel(const float* __restrict__ bo, float* __restrict__ out)
{
    extern __shared__ float sm[];
    gemm_core(g_o, g_wor, bo, out, 1024, 1024, blockIdx.y * 128, blockIdx.x * 128,
              blockIdx.x * 128, sm);
}

// ------------------------- fused flash attention ----------------------------
// CTA: one (b,h,qtile) = 128 queries x 1024 keys. 8 warps = 4 m-groups x 2 n-halves;
// warp tile 32 rows x 64 key cols (halves per-warp smem bytes vs R1).
// Cross-warp (n-half pair) softmax via redM/redS smem exchange.
// smem: Qs[128][132] Ks[128][132](reused as P) Vs[128][136] red[512] = 206848 B.
__global__ __launch_bounds__(256)
void attn_kernel()
{
    extern __shared__ float sm[];
    float (*Qs)[132] = (float(*)[132])sm;
    float (*Ks)[132] = (float(*)[132])(sm + 128 * 132);
    float (*Vs)[136] = (float(*)[136])(sm + 2 * 128 * 132);
    float* redM = sm + 2 * 128 * 132 + 128 * 136;   // [2][128]
    float* redS = redM + 256;                        // [2][128]

    const int tid  = threadIdx.x;
    const int lane = tid & 31;
    const int w    = tid >> 5;
    const int la3  = lane & 3;
    const int lg4  = lane >> 2;
    const int mg   = w & 3;          // m-group (32 rows)
    const int nh   = w >> 2;         // n-half (64 cols)
    const int R    = mg * 32;

    const int bh = blockIdx.x;       // 0..15
    const int qt = blockIdx.y;       // 0..7
    const int b  = bh >> 3;
    const int h  = bh & 7;

    const float scale = 0.088388347648318447f;   // 1/sqrt(128)

    const float* Qg = g_q + (size_t)b * SEQ * DMODEL + (size_t)h * 128 * DMODEL + (size_t)qt * 128 * DV;
    const float* Kg = g_k + (size_t)b * SEQ * DV;
    const float* Vg = g_v + (size_t)b * SEQ * DV;
    float*       Og = g_o + (size_t)b * SEQ * DMODEL + (size_t)h * 128 * DMODEL + (size_t)qt * 128 * DV;

    // load Q tile (pre-scaled, tf32-rounded), float4 stores (row strides 16B-aligned)
#pragma unroll
    for (int i = 0; i < 16; i++) {
        int vid = tid + i * 256;
        int r = vid >> 5, cc = (vid & 31) * 4;
        float4 f = *(const float4*)&Qg[(size_t)r * 128 + cc];
        f.x = tf32r(f.x * scale); f.y = tf32r(f.y * scale);
        f.z = tf32r(f.z * scale); f.w = tf32r(f.w * scale);
        *(float4*)&Qs[r][cc] = f;
    }

    float oacc[2][8][4];
#pragma unroll
    for (int mt = 0; mt < 2; mt++)
#pragma unroll
        for (int nt = 0; nt < 8; nt++)
#pragma unroll
            for (int i = 0; i < 4; i++) oacc[mt][nt][i] = 0.f;
    float mM[2][2] = {{-1e30f, -1e30f}, {-1e30f, -1e30f}};
    float lS[2][2] = {{0.f, 0.f}, {0.f, 0.f}};

    for (int j = 0; j < 8; j++) {
        __syncthreads();    // prior iter's P/V reads done (and Q visible on j==0)
        // load K, V tiles (tf32-rounded)
#pragma unroll
        for (int i = 0; i < 16; i++) {
            int vid = tid + i * 256;
            int r = vid >> 5, cc = (vid & 31) * 4;
            float4 fk = *(const float4*)&Kg[(size_t)(j * 128 + r) * 128 + cc];
            fk.x = tf32r(fk.x); fk.y = tf32r(fk.y); fk.z = tf32r(fk.z); fk.w = tf32r(fk.w);
            *(float4*)&Ks[r][cc] = fk;
            float4 fv = *(const float4*)&Vg[(size_t)(j * 128 + r) * 128 + cc];
            fv.x = tf32r(fv.x); fv.y = tf32r(fv.y); fv.z = tf32r(fv.z); fv.w = tf32r(fv.w);
            *(float4*)&Vs[r][cc] = fv;
        }
        __syncthreads();

        // GEMM1: S[R..R+32][nh*64..+64] = Q @ K^T
        float s[2][8][4];
#pragma unroll
        for (int mt = 0; mt < 2; mt++)
#pragma unroll
            for (int nt = 0; nt < 8; nt++)
#pragma unroll
                for (int i = 0; i < 4; i++) s[mt][nt][i] = 0.f;

#pragma unroll
        for (int kk = 0; kk < 16; kk++) {
            const int k0 = kk * 8;
            unsigned a[2][4];
#pragma unroll
            for (int mt = 0; mt < 2; mt++) {
                int r = R + mt * 16 + lg4;
                a[mt][0] = __float_as_uint(Qs[r][k0 + la3]);
                a[mt][1] = __float_as_uint(Qs[r + 8][k0 + la3]);
                a[mt][2] = __float_as_uint(Qs[r][k0 + la3 + 4]);
                a[mt][3] = __float_as_uint(Qs[r + 8][k0 + la3 + 4]);
            }
#pragma unroll
            for (int nt = 0; nt < 8; nt++) {
                int cn = nh * 64 + nt * 8 + lg4;
                unsigned bb[2];
                bb[0] = __float_as_uint(Ks[cn][k0 + la3]);
                bb[1] = __float_as_uint(Ks[cn][k0 + la3 + 4]);
                mma_tf32(s[0][nt], a[0], bb);
                mma_tf32(s[1][nt], a[1], bb);
            }
        }

        // ---- softmax: local (64-col) max, quad reduce, exchange with partner warp ----
        float rm[2][2] = {{-1e30f, -1e30f}, {-1e30f, -1e30f}};
#pragma unroll
        for (int mt = 0; mt < 2; mt++)
#pragma unroll
            for (int nt = 0; nt < 8; nt++) {
                rm[mt][0] = fmaxf(rm[mt][0], fmaxf(s[mt][nt][0], s[mt][nt][1]));
                rm[mt][1] = fmaxf(rm[mt][1], fmaxf(s[mt][nt][2], s[mt][nt][3]));
            }
#pragma unroll
        for (int mt = 0; mt < 2; mt++)
#pragma unroll
            for (int hh = 0; hh < 2; hh++) {
                rm[mt][hh] = fmaxf(rm[mt][hh], __shfl_xor_sync(0xffffffffu, rm[mt][hh], 1));
                rm[mt][hh] = fmaxf(rm[mt][hh], __shfl_xor_sync(0xffffffffu, rm[mt][hh], 2));
            }
        if (la3 == 0) {
#pragma unroll
            for (int mt = 0; mt < 2; mt++)
#pragma unroll
                for (int hh = 0; hh < 2; hh++)
                    redM[nh * 128 + R + mt * 16 + hh * 8 + lg4] = rm[mt][hh];
        }
        __syncthreads();   // also guarantees all warps finished GEMM1 reads of Ks

        float al[2][2];
#pragma unroll
        for (int mt = 0; mt < 2; mt++)
#pragma unroll
            for (int hh = 0; hh < 2; hh++) {
                float other = redM[(nh ^ 1) * 128 + R + mt * 16 + hh * 8 + lg4];
                float mnew  = fmaxf(mM[mt][hh], fmaxf(rm[mt][hh], other));
                al[mt][hh]  = __expf(mM[mt][hh] - mnew);
                mM[mt][hh]  = mnew;
            }

        float rs[2][2] = {{0.f, 0.f}, {0.f, 0.f}};
#pragma unroll
        for (int mt = 0; mt < 2; mt++)
#pragma unroll
            for (int nt = 0; nt < 8; nt++) {
                s[mt][nt][0] = __expf(s[mt][nt][0] - mM[mt][0]);
                s[mt][nt][1] = __expf(s[mt][nt][1] - mM[mt][0]);
                s[mt][nt][2] = __expf(s[mt][nt][2] - mM[mt][1]);
                s[mt][nt][3] = __expf(s[mt][nt][3] - mM[mt][1]);
                rs[mt][0] += s[mt][nt][0] + s[mt][nt][1];
                rs[mt][1] += s[mt][nt][2] + s[mt][nt][3];
            }
#pragma unroll
        for (int mt = 0; mt < 2; mt++)
#pragma unroll
            for (int hh = 0; hh < 2; hh++) {
                rs[mt][hh] += __shfl_xor_sync(0xffffffffu, rs[mt][hh], 1);
                rs[mt][hh] += __shfl_xor_sync(0xffffffffu, rs[mt][hh], 2);
            }
        if (la3 == 0) {
#pragma unroll
            for (int mt = 0; mt < 2; mt++)
#pragma unroll
                for (int hh = 0; hh < 2; hh++)
                    redS[nh * 128 + R + mt * 16 + hh * 8 + lg4] = rs[mt][hh];
        }
        __syncthreads();

#pragma unroll
        for (int mt = 0; mt < 2; mt++)
#pragma unroll
            for (int hh = 0; hh < 2; hh++) {
                float other = redS[(nh ^ 1) * 128 + R + mt * 16 + hh * 8 + lg4];
                lS[mt][hh] = lS[mt][hh] * al[mt][hh] + rs[mt][hh] + other;
            }
#pragma unroll
        for (int mt = 0; mt < 2; mt++)
#pragma unroll
            for (int nt = 0; nt < 8; nt++) {
                oacc[mt][nt][0] *= al[mt][0];
                oacc[mt][nt][1] *= al[mt][0];
                oacc[mt][nt][2] *= al[mt][1];
                oacc[mt][nt][3] *= al[mt][1];
            }

        // write P into Ks buffer (tf32-rounded), float2 stores
#pragma unroll
        for (int mt = 0; mt < 2; mt++)
#pragma unroll
            for (int nt = 0; nt < 8; nt++) {
                int r  = R + mt * 16 + lg4;
                int pc = nh * 64 + nt * 8 + la3 * 2;
                *(float2*)&Ks[r][pc]     = make_float2(tf32r(s[mt][nt][0]), tf32r(s[mt][nt][1]));
                *(float2*)&Ks[r + 8][pc] = make_float2(tf32r(s[mt][nt][2]), tf32r(s[mt][nt][3]));
            }
        __syncthreads();

        // GEMM2: O[R..+32][nh*64..+64] += P[R..+32][0..128] @ V[0..128][nh*64..+64]
#pragma unroll
        for (int kk = 0; kk < 16; kk++) {
            const int k0 = kk * 8;
            unsigned a[2][4];
#pragma unroll
            for (int mt = 0; mt < 2; mt++) {
                int r = R + mt * 16 + lg4;
                a[mt][0] = __float_as_uint(Ks[r][k0 + la3]);
                a[mt][1] = __float_as_uint(Ks[r + 8][k0 + la3]);
                a[mt][2] = __float_as_uint(Ks[r][k0 + la3 + 4]);
                a[mt][3] = __float_as_uint(Ks[r + 8][k0 + la3 + 4]);
            }
#pragma unroll
            for (int nt = 0; nt < 8; nt++) {
                int cn = nh * 64 + nt * 8 + lg4;
                unsigned bb[2];
                bb[0] = __float_as_uint(Vs[k0 + la3][cn]);
                bb[1] = __float_as_uint(Vs[k0 + la3 + 4][cn]);
                mma_tf32(oacc[0][nt], a[0], bb);
                mma_tf32(oacc[1][nt], a[1], bb);
            }
        }
    }

    // epilogue: divide by denom, tf32-round (feeds Wo GEMM directly), write
    float inv[2][2];
#pragma unroll
    for (int mt = 0; mt < 2; mt++) {
        inv[mt][0] = 1.f / lS[mt][0];
        inv[mt][1] = 1.f / lS[mt][1];
    }
#pragma unroll
    for (int mt = 0; mt < 2; mt++)
#pragma unroll
        for (int nt = 0; nt < 8; nt++) {
            int r  = R + mt * 16 + lg4;
            int cc = nh * 64 + nt * 8 + la3 * 2;
            *(float2*)&Og[(size_t)r * 128 + cc] =
                make_float2(tf32r(oacc[mt][nt][0] * inv[mt][0]),
                            tf32r(oacc[mt][nt][1] * inv[mt][0]));
            *(float2*)&Og[(size_t)(r + 8) * 128 + cc] =
                make_float2(tf32r(oacc[mt][nt][2] * inv[mt][1]),
                            tf32r(oacc[mt][nt][3] * inv[mt][1]));
        }
}

// ---------------------------------------------------------------------------
extern "C" void kernel_launch(void* const* d_in, const int* in_sizes, int n_in,
                              void* d_out, int out_size)
{
    const float* x  = (const float*)d_in[0];
    const float* Wq = (const float*)d_in[1];
    const float* bq = (const float*)d_in[2];
    const float* Wk = (const float*)d_in[3];
    const float* bk = (const float*)d_in[4];
    const float* Wv = (const float*)d_in[5];
    const float* bv = (const float*)d_in[6];
    const float* Wo = (const float*)d_in[7];
    const float* bo = (const float*)d_in[8];
    float* out = (float*)d_out;

    const int GEMM_SMEM = (2 * 128 * 36 + 2 * 32 * 136) * 4;                 // 71680 B
    const int ATTN_SMEM = (2 * 128 * 132 + 128 * 136 + 512) * 4;             // 206848 B
    cudaFuncSetAttribute(qkv_kernel,  cudaFuncAttributeMaxDynamicSharedMemorySize, GEMM_SMEM);
    cudaFuncSetAttribute(wo_kernel,   cudaFuncAttributeMaxDynamicSharedMemorySize, GEMM_SMEM);
    cudaFuncSetAttribute(attn_kernel, cudaFuncAttributeMaxDynamicSharedMemorySize, ATTN_SMEM);

    // 1. round all inputs to tf32 once
    round_pre<<<512, 256>>>(x, Wq, Wk, Wv, Wo);
    // 2. fused Q|K|V projections (160 CTAs)
    qkv_kernel<<<dim3(10, 16), 128, GEMM_SMEM>>>(bq, bk, bv);
    // 3. attention (128 CTAs)
    attn_kernel<<<dim3(16, 8), 256, ATTN_SMEM>>>();
    // 4. output projection (128 CTAs)
    wo_kernel<<<dim3(8, 16), 128, GEMM_SMEM>>>(bo, out);
}

// round 5
// speedup vs baseline: 1.4253x; 1.0323x over previous
#include <cuda_runtime.h>

#define SEQ    1024
#define DMODEL 1024
#define DV     128

// ------------------------- scratch (__device__ globals) ---------------------
__device__ float g_xr [2 * SEQ * DMODEL];     // tf32-rounded x
__device__ float g_wqr[DMODEL * DMODEL];
__device__ float g_wkr[DMODEL * DV];
__device__ float g_wvr[DMODEL * DV];
__device__ float g_wor[DMODEL * DMODEL];
__device__ float g_q  [2 * SEQ * DMODEL];
__device__ float g_k  [2 * SEQ * DV];
__device__ float g_v  [2 * SEQ * DV];
__device__ float g_o  [2 * SEQ * DMODEL];

// round-to-nearest tf32
__device__ __forceinline__ float tf32r(float x) {
    asm("cvt.rna.tf32.f32 %0, %0;" : "+f"(x));
    return x;
}

__device__ __forceinline__ void mma_tf32(float c[4], const unsigned a[4], const unsigned b[2]) {
    asm volatile(
        "mma.sync.aligned.m16n8k8.row.col.f32.tf32.tf32.f32 "
        "{%0,%1,%2,%3}, {%4,%5,%6,%7}, {%8,%9}, {%0,%1,%2,%3};\n"
        : "+f"(c[0]), "+f"(c[1]), "+f"(c[2]), "+f"(c[3])
        : "r"(a[0]), "r"(a[1]), "r"(a[2]), "r"(a[3]), "r"(b[0]), "r"(b[1]));
}

// ------------------------- prepass: round inputs to tf32 --------------------
__global__ void round_pre(const float* __restrict__ x,  const float* __restrict__ wq,
                          const float* __restrict__ wk, const float* __restrict__ wv,
                          const float* __restrict__ wo)
{
    const size_t E0 = 524288;            // x      float4 count
    const size_t E1 = E0 + 262144;       // wq
    const size_t E2 = E1 + 32768;        // wk
    const size_t E3 = E2 + 32768;        // wv
    const size_t E4 = E3 + 262144;       // wo
    size_t i = (size_t)blockIdx.x * blockDim.x + threadIdx.x;
    size_t stride = (size_t)gridDim.x * blockDim.x;
    for (; i < E4; i += stride) {
        const float4* s; float4* d; size_t off;
        if      (i < E0) { s = (const float4*)x;  d = (float4*)g_xr;  off = i;      }
        else if (i < E1) { s = (const float4*)wq; d = (float4*)g_wqr; off = i - E0; }
        else if (i < E2) { s = (const float4*)wk; d = (float4*)g_wkr; off = i - E1; }
        else if (i < E3) { s = (const float4*)wv; d = (float4*)g_wvr; off = i - E2; }
        else             { s = (const float4*)wo; d = (float4*)g_wor; off = i - E3; }
        float4 f = s[off];
        f.x = tf32r(f.x); f.y = tf32r(f.y); f.z = tf32r(f.z); f.w = tf32r(f.w);
        d[off] = f;
    }
}

// ------------------------- GEMM core (BM=128 BN=128 BK=32) ------------------
// 256 threads / 8 warps, warp tile 64x32 (2 warps per SMSP -> latency hiding),
// cp.async 2-stage double buffer, 2 CTAs/SM. A,B pre-rounded to tf32.
// smem: As[2][128][36] + Bs[2][32][136] = 71680 B (x2 CTAs = 143 KB < 227 KB).

__device__ __forceinline__ void cpa16(float* dst, const float* src) {
    unsigned d = (unsigned)__cvta_generic_to_shared(dst);
    asm volatile("cp.async.cg.shared.global [%0], [%1], 16;\n" :: "r"(d), "l"(src) : "memory");
}

__device__ __forceinline__ void gemm_load_tiles(float* sm, int s,
                                                const float* __restrict__ A,
                                                const float* __restrict__ Bm,
                                                int N, int bm, int bn, int kb, int tid)
{
    float* As = sm + s * (128 * 36);
    float* Bs = sm + 2 * 128 * 36 + s * (32 * 136);
#pragma unroll
    for (int i = 0; i < 4; i++) {                 // A: 128x32 -> 1024 16B chunks
        int id = tid + i * 256;
        int r = id >> 3, c4 = (id & 7) * 4;
        cpa16(As + r * 36 + c4, A + (size_t)(bm + r) * 1024 + kb + c4);
    }
#pragma unroll
    for (int i = 0; i < 4; i++) {                 // B: 32x128
        int id = tid + i * 256;
        int r = id >> 5, c4 = (id & 31) * 4;
        cpa16(Bs + r * 136 + c4, Bm + (size_t)(kb + r) * N + bn + c4);
    }
    asm volatile("cp.async.commit_group;\n" ::: "memory");
}

__device__ __forceinline__ void gemm_core(const float* __restrict__ A,
                                          const float* __restrict__ Bm,
                                          const float* __restrict__ bias,
                                          float* __restrict__ C,
                                          int N, int Nc, int bm, int bn, int bnc,
                                          float* sm)
{
    const int tid  = threadIdx.x;
    const int lane = tid & 31;
    const int w    = tid >> 5;
    const int la3  = lane & 3;
    const int lg4  = lane >> 2;
    const int wm   = (w & 1) * 64;       // 2 m-groups
    const int wn   = (w >> 1) * 32;      // 4 n-groups

    float c[4][4][4];
#pragma unroll
    for (int mt = 0; mt < 4; mt++)
#pragma unroll
        for (int nt = 0; nt < 4; nt++)
#pragma unroll
            for (int i = 0; i < 4; i++) c[mt][nt][i] = 0.f;

    gemm_load_tiles(sm, 0, A, Bm, N, bm, bn, 0, tid);

    for (int kbi = 0; kbi < 32; kbi++) {
        const int s = kbi & 1;
        asm volatile("cp.async.wait_group 0;\n" ::: "memory");
        __syncthreads();                           // stage s ready; all warps past stage s^1
        if (kbi < 31)
            gemm_load_tiles(sm, s ^ 1, A, Bm, N, bm, bn, (kbi + 1) * 32, tid);

        float (*As)[36]  = (float(*)[36])(sm + s * (128 * 36));
        float (*Bs)[136] = (float(*)[136])(sm + 2 * 128 * 36 + s * (32 * 136));
#pragma unroll
        for (int kk = 0; kk < 4; kk++) {
            const int k0 = kk * 8;
            unsigned a[4][4];
#pragma unroll
            for (int mt = 0; mt < 4; mt++) {
                int r = wm + mt * 16 + lg4;
                a[mt][0] = __float_as_uint(As[r][k0 + la3]);
                a[mt][1] = __float_as_uint(As[r + 8][k0 + la3]);
                a[mt][2] = __float_as_uint(As[r][k0 + la3 + 4]);
                a[mt][3] = __float_as_uint(As[r + 8][k0 + la3 + 4]);
            }
            unsigned b[4][2];
#pragma unroll
            for (int nt = 0; nt < 4; nt++) {
                int cn = wn + nt * 8 + lg4;
                b[nt][0] = __float_as_uint(Bs[k0 + la3][cn]);
                b[nt][1] = __float_as_uint(Bs[k0 + la3 + 4][cn]);
            }
#pragma unroll
            for (int mt = 0; mt < 4; mt++)
#pragma unroll
                for (int nt = 0; nt < 4; nt++)
                    mma_tf32(c[mt][nt], a[mt], b[nt]);
        }
    }

    // epilogue: +bias, fp32 store
#pragma unroll
    for (int mt = 0; mt < 4; mt++) {
#pragma unroll
        for (int nt = 0; nt < 4; nt++) {
            int row = bm + wm + mt * 16 + lg4;
            int cn  = wn + nt * 8 + la3 * 2;
            float b0 = bias[bn + cn], b1 = bias[bn + cn + 1];
            float2 v0 = make_float2(c[mt][nt][0] + b0, c[mt][nt][1] + b1);
            float2 v1 = make_float2(c[mt][nt][2] + b0, c[mt][nt][3] + b1);
            *(float2*)&C[(size_t)row * Nc + bnc + cn]       = v0;
            *(float2*)&C[(size_t)(row + 8) * Nc + bnc + cn] = v1;
        }
    }
}

// Fused QKV projection: grid (10, 16). bx<8 -> Q col-block, bx==8 -> K, bx==9 -> V.
__global__ __launch_bounds__(256, 2)
void qkv_kernel(const float* __restrict__ bq, const float* __restrict__ bk,
                const float* __restrict__ bv)
{
    extern __shared__ float sm[];
    const int bx = blockIdx.x;
    const int bm = blockIdx.y * 128;
    if (bx < 8)
        gemm_core(g_xr, g_wqr, bq, g_q, 1024, 1024, bm, bx * 128, bx * 128, sm);
    else if (bx == 8)
        gemm_core(g_xr, g_wkr, bk, g_k, 128, 128, bm, 0, 0, sm);
    else
        gemm_core(g_xr, g_wvr, bv, g_v, 128, 128, bm, 0, 0, sm);
}

// Output projection: grid (8, 16).
__global__ __launch_bounds__(256, 2)
void wo_kernel(const float* __restrict__ bo, float* __restrict__ out)
{
    extern __shared__ float sm[];
    gemm_core(g_o, g_wor, bo, out, 1024, 1024, blockIdx.y * 128, blockIdx.x * 128,
              blockIdx.x * 128, sm);
}

// ------------------------- fused flash attention ----------------------------
// CTA: one (b,h,qtile) = 128 queries x 1024 keys. 8 warps = 4 m-groups x 2 n-halves;
// warp tile 32 rows x 64 key cols. Cross-warp softmax via redM/redS smem exchange.
// smem: Qs[128][132] Ks[128][132](reused as P) Vs[128][136] red[512] = 206848 B.
__global__ __launch_bounds__(256)
void attn_kernel()
{
    extern __shared__ float sm[];
    float (*Qs)[132] = (float(*)[132])sm;
    float (*Ks)[132] = (float(*)[132])(sm + 128 * 132);
    float (*Vs)[136] = (float(*)[136])(sm + 2 * 128 * 132);
    float* redM = sm + 2 * 128 * 132 + 128 * 136;   // [2][128]
    float* redS = redM + 256;                        // [2][128]

    const int tid  = threadIdx.x;
    const int lane = tid & 31;
    const int w    = tid >> 5;
    const int la3  = lane & 3;
    const int lg4  = lane >> 2;
    const int mg   = w & 3;          // m-group (32 rows)
    const int nh   = w >> 2;         // n-half (64 cols)
    const int R    = mg * 32;

    const int bh = blockIdx.x;       // 0..15
    const int qt = blockIdx.y;       // 0..7
    const int b  = bh >> 3;
    const int h  = bh & 7;

    const float scale = 0.088388347648318447f;   // 1/sqrt(128)

    const float* Qg = g_q + (size_t)b * SEQ * DMODEL + (size_t)h * 128 * DMODEL + (size_t)qt * 128 * DV;
    const float* Kg = g_k + (size_t)b * SEQ * DV;
    const float* Vg = g_v + (size_t)b * SEQ * DV;
    float*       Og = g_o + (size_t)b * SEQ * DMODEL + (size_t)h * 128 * DMODEL + (size_t)qt * 128 * DV;

    // load Q tile (pre-scaled, tf32-rounded), float4 stores
#pragma unroll
    for (int i = 0; i < 16; i++) {
        int vid = tid + i * 256;
        int r = vid >> 5, cc = (vid & 31) * 4;
        float4 f = *(const float4*)&Qg[(size_t)r * 128 + cc];
        f.x = tf32r(f.x * scale); f.y = tf32r(f.y * scale);
        f.z = tf32r(f.z * scale); f.w = tf32r(f.w * scale);
        *(float4*)&Qs[r][cc] = f;
    }

    float oacc[2][8][4];
#pragma unroll
    for (int mt = 0; mt < 2; mt++)
#pragma unroll
        for (int nt = 0; nt < 8; nt++)
#pragma unroll
            for (int i = 0; i < 4; i++) oacc[mt][nt][i] = 0.f;
    float mM[2][2] = {{-1e30f, -1e30f}, {-1e30f, -1e30f}};
    float lS[2][2] = {{0.f, 0.f}, {0.f, 0.f}};

    for (int j = 0; j < 8; j++) {
        __syncthreads();    // prior iter's P/V reads done (and Q visible on j==0)
        // load K, V tiles (tf32-rounded)
#pragma unroll
        for (int i = 0; i < 16; i++) {
            int vid = tid + i * 256;
            int r = vid >> 5, cc = (vid & 31) * 4;
            float4 fk = *(const float4*)&Kg[(size_t)(j * 128 + r) * 128 + cc];
            fk.x = tf32r(fk.x); fk.y = tf32r(fk.y); fk.z = tf32r(fk.z); fk.w = tf32r(fk.w);
            *(float4*)&Ks[r][cc] = fk;
            float4 fv = *(const float4*)&Vg[(size_t)(j * 128 + r) * 128 + cc];
            fv.x = tf32r(fv.x); fv.y = tf32r(fv.y); fv.z = tf32r(fv.z); fv.w = tf32r(fv.w);
            *(float4*)&Vs[r][cc] = fv;
        }
        __syncthreads();

        // GEMM1: S[R..R+32][nh*64..+64] = Q @ K^T
        float s[2][8][4];
#pragma unroll
        for (int mt = 0; mt < 2; mt++)
#pragma unroll
            for (int nt = 0; nt < 8; nt++)
#pragma unroll
                for (int i = 0; i < 4; i++) s[mt][nt][i] = 0.f;

#pragma unroll
        for (int kk = 0; kk < 16; kk++) {
            const int k0 = kk * 8;
            unsigned a[2][4];
#pragma unroll
            for (int mt = 0; mt < 2; mt++) {
                int r = R + mt * 16 + lg4;
                a[mt][0] = __float_as_uint(Qs[r][k0 + la3]);
                a[mt][1] = __float_as_uint(Qs[r + 8][k0 + la3]);
                a[mt][2] = __float_as_uint(Qs[r][k0 + la3 + 4]);
                a[mt][3] = __float_as_uint(Qs[r + 8][k0 + la3 + 4]);
            }
#pragma unroll
            for (int nt = 0; nt < 8; nt++) {
                int cn = nh * 64 + nt * 8 + lg4;
                unsigned bb[2];
                bb[0] = __float_as_uint(Ks[cn][k0 + la3]);
                bb[1] = __float_as_uint(Ks[cn][k0 + la3 + 4]);
                mma_tf32(s[0][nt], a[0], bb);
                mma_tf32(s[1][nt], a[1], bb);
            }
        }

        // ---- softmax: local (64-col) max, quad reduce, exchange with partner warp ----
        float rm[2][2] = {{-1e30f, -1e30f}, {-1e30f, -1e30f}};
#pragma unroll
        for (int mt = 0; mt < 2; mt++)
#pragma unroll
            for (int nt = 0; nt < 8; nt++) {
                rm[mt][0] = fmaxf(rm[mt][0], fmaxf(s[mt][nt][0], s[mt][nt][1]));
                rm[mt][1] = fmaxf(rm[mt][1], fmaxf(s[mt][nt][2], s[mt][nt][3]));
            }
#pragma unroll
        for (int mt = 0; mt < 2; mt++)
#pragma unroll
            for (int hh = 0; hh < 2; hh++) {
                rm[mt][hh] = fmaxf(rm[mt][hh], __shfl_xor_sync(0xffffffffu, rm[mt][hh], 1));
                rm[mt][hh] = fmaxf(rm[mt][hh], __shfl_xor_sync(0xffffffffu, rm[mt][hh], 2));
            }
        if (la3 == 0) {
#pragma unroll
            for (int mt = 0; mt < 2; mt++)
#pragma unroll
                for (int hh = 0; hh < 2; hh++)
                    redM[nh * 128 + R + mt * 16 + hh * 8 + lg4] = rm[mt][hh];
        }
        __syncthreads();   // also guarantees all warps finished GEMM1 reads of Ks

        float al[2][2];
#pragma unroll
        for (int mt = 0; mt < 2; mt++)
#pragma unroll
            for (int hh = 0; hh < 2; hh++) {
                float other = redM[(nh ^ 1) * 128 + R + mt * 16 + hh * 8 + lg4];
                float mnew  = fmaxf(mM[mt][hh], fmaxf(rm[mt][hh], other));
                al[mt][hh]  = __expf(mM[mt][hh] - mnew);
                mM[mt][hh]  = mnew;
            }

        float rs[2][2] = {{0.f, 0.f}, {0.f, 0.f}};
#pragma unroll
        for (int mt = 0; mt < 2; mt++)
#pragma unroll
            for (int nt = 0; nt < 8; nt++) {
                s[mt][nt][0] = __expf(s[mt][nt][0] - mM[mt][0]);
                s[mt][nt][1] = __expf(s[mt][nt][1] - mM[mt][0]);
                s[mt][nt][2] = __expf(s[mt][nt][2] - mM[mt][1]);
                s[mt][nt][3] = __expf(s[mt][nt][3] - mM[mt][1]);
                rs[mt][0] += s[mt][nt][0] + s[mt][nt][1];
                rs[mt][1] += s[mt][nt][2] + s[mt][nt][3];
            }
#pragma unroll
        for (int mt = 0; mt < 2; mt++)
#pragma unroll
            for (int hh = 0; hh < 2; hh++) {
                rs[mt][hh] += __shfl_xor_sync(0xffffffffu, rs[mt][hh], 1);
                rs[mt][hh] += __shfl_xor_sync(0xffffffffu, rs[mt][hh], 2);
            }
        if (la3 == 0) {
#pragma unroll
            for (int mt = 0; mt < 2; mt++)
#pragma unroll
                for (int hh = 0; hh < 2; hh++)
                    redS[nh * 128 + R + mt * 16 + hh * 8 + lg4] = rs[mt][hh];
        }
        __syncthreads();

#pragma unroll
        for (int mt = 0; mt < 2; mt++)
#pragma unroll
            for (int hh = 0; hh < 2; hh++) {
                float other = redS[(nh ^ 1) * 128 + R + mt * 16 + hh * 8 + lg4];
                lS[mt][hh] = lS[mt][hh] * al[mt][hh] + rs[mt][hh] + other;
            }
#pragma unroll
        for (int mt = 0; mt < 2; mt++)
#pragma unroll
            for (int nt = 0; nt < 8; nt++) {
                oacc[mt][nt][0] *= al[mt][0];
                oacc[mt][nt][1] *= al[mt][0];
                oacc[mt][nt][2] *= al[mt][1];
                oacc[mt][nt][3] *= al[mt][1];
            }

        // write P into Ks buffer (tf32-rounded), float2 stores
#pragma unroll
        for (int mt = 0; mt < 2; mt++)
#pragma unroll
            for (int nt = 0; nt < 8; nt++) {
                int r  = R + mt * 16 + lg4;
                int pc = nh * 64 + nt * 8 + la3 * 2;
                *(float2*)&Ks[r][pc]     = make_float2(tf32r(s[mt][nt][0]), tf32r(s[mt][nt][1]));
                *(float2*)&Ks[r + 8][pc] = make_float2(tf32r(s[mt][nt][2]), tf32r(s[mt][nt][3]));
            }
        __syncthreads();

        // GEMM2: O[R..+32][nh*64..+64] += P[R..+32][0..128] @ V[0..128][nh*64..+64]
#pragma unroll
        for (int kk = 0; kk < 16; kk++) {
            const int k0 = kk * 8;
            unsigned a[2][4];
#pragma unroll
            for (int mt = 0; mt < 2; mt++) {
                int r = R + mt * 16 + lg4;
                a[mt][0] = __float_as_uint(Ks[r][k0 + la3]);
                a[mt][1] = __float_as_uint(Ks[r + 8][k0 + la3]);
                a[mt][2] = __float_as_uint(Ks[r][k0 + la3 + 4]);
                a[mt][3] = __float_as_uint(Ks[r + 8][k0 + la3 + 4]);
            }
#pragma unroll
            for (int nt = 0; nt < 8; nt++) {
                int cn = nh * 64 + nt * 8 + lg4;
                unsigned bb[2];
                bb[0] = __float_as_uint(Vs[k0 + la3][cn]);
                bb[1] = __float_as_uint(Vs[k0 + la3 + 4][cn]);
                mma_tf32(oacc[0][nt], a[0], bb);
                mma_tf32(oacc[1][nt], a[1], bb);
            }
        }
    }

    // epilogue: divide by denom, tf32-round (feeds Wo GEMM directly), write
    float inv[2][2];
#pragma unroll
    for (int mt = 0; mt < 2; mt++) {
        inv[mt][0] = 1.f / lS[mt][0];
        inv[mt][1] = 1.f / lS[mt][1];
    }
#pragma unroll
    for (int mt = 0; mt < 2; mt++)
#pragma unroll
        for (int nt = 0; nt < 8; nt++) {
            int r  = R + mt * 16 + lg4;
            int cc = nh * 64 + nt * 8 + la3 * 2;
            *(float2*)&Og[(size_t)r * 128 + cc] =
                make_float2(tf32r(oacc[mt][nt][0] * inv[mt][0]),
                            tf32r(oacc[mt][nt][1] * inv[mt][0]));
            *(float2*)&Og[(size_t)(r + 8) * 128 + cc] =
                make_float2(tf32r(oacc[mt][nt][2] * inv[mt][1]),
                            tf32r(oacc[mt][nt][3] * inv[mt][1]));
        }
}

// ---------------------------------------------------------------------------
extern "C" void kernel_launch(void* const* d_in, const int* in_sizes, int n_in,
                              void* d_out, int out_size)
{
    const float* x  = (const float*)d_in[0];
    const float* Wq = (const float*)d_in[1];
    const float* bq = (const float*)d_in[2];
    const float* Wk = (const float*)d_in[3];
    const float* bk = (const float*)d_in[4];
    const float* Wv = (const float*)d_in[5];
    const float* bv = (const float*)d_in[6];
    const float* Wo = (const float*)d_in[7];
    const float* bo = (const float*)d_in[8];
    float* out = (float*)d_out;

    const int GEMM_SMEM = (2 * 128 * 36 + 2 * 32 * 136) * 4;                 // 71680 B
    const int ATTN_SMEM = (2 * 128 * 132 + 128 * 136 + 512) * 4;             // 206848 B
    cudaFuncSetAttribute(qkv_kernel,  cudaFuncAttributeMaxDynamicSharedMemorySize, GEMM_SMEM);
    cudaFuncSetAttribute(wo_kernel,   cudaFuncAttributeMaxDynamicSharedMemorySize, GEMM_SMEM);
    cudaFuncSetAttribute(attn_kernel, cudaFuncAttributeMaxDynamicSharedMemorySize, ATTN_SMEM);

    // 1. round all inputs to tf32 once
    round_pre<<<512, 256>>>(x, Wq, Wk, Wv, Wo);
    // 2. fused Q|K|V projections (160 CTAs)
    qkv_kernel<<<dim3(10, 16), 256, GEMM_SMEM>>>(bq, bk, bv);
    // 3. attention (128 CTAs)
    attn_kernel<<<dim3(16, 8), 256, ATTN_SMEM>>>();
    // 4. output projection (128 CTAs)
    wo_kernel<<<dim3(8, 16), 256, GEMM_SMEM>>>(bo, out);
}

// round 10
// speedup vs baseline: 1.4774x; 1.0366x over previous
#include <cuda_runtime.h>

#define SEQ    1024
#define DMODEL 1024
#define DV     128

// ------------------------- scratch (__device__ globals) ---------------------
__device__ float g_xr [2 * SEQ * DMODEL];     // tf32-rounded x
__device__ float g_wqr[DMODEL * DMODEL];
__device__ float g_wkr[DMODEL * DV];
__device__ float g_wvr[DMODEL * DV];
__device__ float g_wor[DMODEL * DMODEL];
__device__ float g_q  [2 * SEQ * DMODEL];
__device__ float g_k  [2 * SEQ * DV];     // tf32-rounded by producer
__device__ float g_v  [2 * SEQ * DV];     // tf32-rounded by producer
__device__ float g_o  [2 * SEQ * DMODEL]; // tf32-rounded by attn epilogue

// round-to-nearest tf32
__device__ __forceinline__ float tf32r(float x) {
    asm("cvt.rna.tf32.f32 %0, %0;" : "+f"(x));
    return x;
}

__device__ __forceinline__ void mma_tf32(float c[4], const unsigned a[4], const unsigned b[2]) {
    asm volatile(
        "mma.sync.aligned.m16n8k8.row.col.f32.tf32.tf32.f32 "
        "{%0,%1,%2,%3}, {%4,%5,%6,%7}, {%8,%9}, {%0,%1,%2,%3};\n"
        : "+f"(c[0]), "+f"(c[1]), "+f"(c[2]), "+f"(c[3])
        : "r"(a[0]), "r"(a[1]), "r"(a[2]), "r"(a[3]), "r"(b[0]), "r"(b[1]));
}

// ------------------------- prepass: round inputs to tf32 --------------------
__global__ void round_pre(const float* __restrict__ x,  const float* __restrict__ wq,
                          const float* __restrict__ wk, const float* __restrict__ wv,
                          const float* __restrict__ wo)
{
    const size_t E0 = 524288;            // x      float4 count
    const size_t E1 = E0 + 262144;       // wq
    const size_t E2 = E1 + 32768;        // wk
    const size_t E3 = E2 + 32768;        // wv
    const size_t E4 = E3 + 262144;       // wo
    size_t i = (size_t)blockIdx.x * blockDim.x + threadIdx.x;
    size_t stride = (size_t)gridDim.x * blockDim.x;
    for (; i < E4; i += stride) {
        const float4* s; float4* d; size_t off;
        if      (i < E0) { s = (const float4*)x;  d = (float4*)g_xr;  off = i;      }
        else if (i < E1) { s = (const float4*)wq; d = (float4*)g_wqr; off = i - E0; }
        else if (i < E2) { s = (const float4*)wk; d = (float4*)g_wkr; off = i - E1; }
        else if (i < E3) { s = (const float4*)wv; d = (float4*)g_wvr; off = i - E2; }
        else             { s = (const float4*)wo; d = (float4*)g_wor; off = i - E3; }
        float4 f = s[off];
        f.x = tf32r(f.x); f.y = tf32r(f.y); f.z = tf32r(f.z); f.w = tf32r(f.w);
        d[off] = f;
    }
}

// ------------------------- GEMM core (BM=128 BN=64 BK=32) -------------------
// 256 threads / 8 warps (4 m-groups x 2 n-groups), warp tile 32x32.
// Grids >= 256 CTAs -> 2 CTAs/SM genuinely co-resident (the R5 occupancy fix).
// cp.async 2-stage double buffer. K fixed at 1024. A,B pre-rounded to tf32.
// smem: As[2][128][36] + Bs[2][32][72] = 55296 B (x2 CTAs = 108 KB < 227 KB).

__device__ __forceinline__ void cpa16(float* dst, const float* src) {
    unsigned d = (unsigned)__cvta_generic_to_shared(dst);
    asm volatile("cp.async.cg.shared.global [%0], [%1], 16;\n" :: "r"(d), "l"(src) : "memory");
}

#define AS_STAGE (128 * 36)
#define BS_STAGE (32 * 72)
#define BS_BASE  (2 * AS_STAGE)

__device__ __forceinline__ void gemm_load_tiles(float* sm, int s,
                                                const float* __restrict__ A,
                                                const float* __restrict__ Bm,
                                                int N, int bm, int bn, int kb, int tid)
{
    float* As = sm + s * AS_STAGE;
    float* Bs = sm + BS_BASE + s * BS_STAGE;
#pragma unroll
    for (int i = 0; i < 4; i++) {                 // A: 128x32 -> 1024 16B chunks
        int id = tid + i * 256;
        int r = id >> 3, c4 = (id & 7) * 4;
        cpa16(As + r * 36 + c4, A + (size_t)(bm + r) * 1024 + kb + c4);
    }
#pragma unroll
    for (int i = 0; i < 2; i++) {                 // B: 32x64 -> 512 16B chunks
        int id = tid + i * 256;
        int r = id >> 4, c4 = (id & 15) * 4;
        cpa16(Bs + r * 72 + c4, Bm + (size_t)(kb + r) * N + bn + c4);
    }
    asm volatile("cp.async.commit_group;\n" ::: "memory");
}

__device__ __forceinline__ void gemm_core(const float* __restrict__ A,
                                          const float* __restrict__ Bm,
                                          const float* __restrict__ bias,
                                          float* __restrict__ C,
                                          int N, int Nc, int bm, int bn, int bnc,
                                          float* sm, bool ROUND)
{
    const int tid  = threadIdx.x;
    const int lane = tid & 31;
    const int w    = tid >> 5;
    const int la3  = lane & 3;
    const int lg4  = lane >> 2;
    const int wm   = (w & 3) * 32;       // 4 m-groups
    const int wn   = (w >> 2) * 32;      // 2 n-groups

    float c[2][4][4];
#pragma unroll
    for (int mt = 0; mt < 2; mt++)
#pragma unroll
        for (int nt = 0; nt < 4; nt++)
#pragma unroll
            for (int i = 0; i < 4; i++) c[mt][nt][i] = 0.f;

    gemm_load_tiles(sm, 0, A, Bm, N, bm, bn, 0, tid);

    for (int kbi = 0; kbi < 32; kbi++) {
        const int s = kbi & 1;
        asm volatile("cp.async.wait_group 0;\n" ::: "memory");
        __syncthreads();                           // stage s ready; all warps past stage s^1
        if (kbi < 31)
            gemm_load_tiles(sm, s ^ 1, A, Bm, N, bm, bn, (kbi + 1) * 32, tid);

        float (*As)[36] = (float(*)[36])(sm + s * AS_STAGE);
        float (*Bs)[72] = (float(*)[72])(sm + BS_BASE + s * BS_STAGE);
#pragma unroll
        for (int kk = 0; kk < 4; kk++) {
            const int k0 = kk * 8;
            unsigned a[2][4];
#pragma unroll
            for (int mt = 0; mt < 2; mt++) {
                int r = wm + mt * 16 + lg4;
                a[mt][0] = __float_as_uint(As[r][k0 + la3]);
                a[mt][1] = __float_as_uint(As[r + 8][k0 + la3]);
                a[mt][2] = __float_as_uint(As[r][k0 + la3 + 4]);
                a[mt][3] = __float_as_uint(As[r + 8][k0 + la3 + 4]);
            }
            unsigned b[4][2];
#pragma unroll
            for (int nt = 0; nt < 4; nt++) {
                int cn = wn + nt * 8 + lg4;
                b[nt][0] = __float_as_uint(Bs[k0 + la3][cn]);
                b[nt][1] = __float_as_uint(Bs[k0 + la3 + 4][cn]);
            }
#pragma unroll
            for (int mt = 0; mt < 2; mt++)
#pragma unroll
                for (int nt = 0; nt < 4; nt++)
                    mma_tf32(c[mt][nt], a[mt], b[nt]);
        }
    }

    // epilogue: +bias (optionally tf32-rounded for downstream mma consumers)
#pragma unroll
    for (int mt = 0; mt < 2; mt++) {
#pragma unroll
        for (int nt = 0; nt < 4; nt++) {
            int row = bm + wm + mt * 16 + lg4;
            int cn  = wn + nt * 8 + la3 * 2;
            float b0 = bias[bn + cn], b1 = bias[bn + cn + 1];
            float v00 = c[mt][nt][0] + b0, v01 = c[mt][nt][1] + b1;
            float v10 = c[mt][nt][2] + b0, v11 = c[mt][nt][3] + b1;
            if (ROUND) { v00 = tf32r(v00); v01 = tf32r(v01); v10 = tf32r(v10); v11 = tf32r(v11); }
            *(float2*)&C[(size_t)row * Nc + bnc + cn]       = make_float2(v00, v01);
            *(float2*)&C[(size_t)(row + 8) * Nc + bnc + cn] = make_float2(v10, v11);
        }
    }
}

// Fused QKV projection: grid (20, 16).
// bx<16 -> Q col-tile bx ; bx 16,17 -> K col-tiles ; bx 18,19 -> V col-tiles.
__global__ __launch_bounds__(256, 2)
void qkv_kernel(const float* __restrict__ bq, const float* __restrict__ bk,
                const float* __restrict__ bv)
{
    extern __shared__ float sm[];
    const int bx = blockIdx.x;
    const int bm = blockIdx.y * 128;
    if (bx < 16)
        gemm_core(g_xr, g_wqr, bq, g_q, 1024, 1024, bm, bx * 64, bx * 64, sm, false);
    else if (bx < 18)
        gemm_core(g_xr, g_wkr, bk, g_k, 128, 128, bm, (bx - 16) * 64, (bx - 16) * 64, sm, true);
    else
        gemm_core(g_xr, g_wvr, bv, g_v, 128, 128, bm, (bx - 18) * 64, (bx - 18) * 64, sm, true);
}

// Output projection: grid (16, 16) = 256 CTAs.
__global__ __launch_bounds__(256, 2)
void wo_kernel(const float* __restrict__ bo, float* __restrict__ out)
{
    extern __shared__ float sm[];
    gemm_core(g_o, g_wor, bo, out, 1024, 1024, blockIdx.y * 128, blockIdx.x * 64,
              blockIdx.x * 64, sm, false);
}

// ------------------------- fused flash attention ----------------------------
// CTA: one (b,h,qtile) = 128 queries x 1024 keys. 8 warps = 4 m-groups x 2 n-halves;
// warp tile 32 rows x 64 key cols. Cross-warp softmax via redM/redS smem exchange.
// K/V are tf32-rounded by the producer -> loads are pure cp.async 16B copies.
// Split-wait: K and V are separate commit groups; GEMM1 starts once K lands,
// V's latency hides behind GEMM1 (wait deferred to the softmax barrier).
// smem: Qs[128][132] Ks[128][132](reused as P) Vs[128][136] red[512] = 206848 B.
__global__ __launch_bounds__(256)
void attn_kernel()
{
    extern __shared__ float sm[];
    float (*Qs)[132] = (float(*)[132])sm;
    float (*Ks)[132] = (float(*)[132])(sm + 128 * 132);
    float (*Vs)[136] = (float(*)[136])(sm + 2 * 128 * 132);
    float* redM = sm + 2 * 128 * 132 + 128 * 136;   // [2][128]
    float* redS = redM + 256;                        // [2][128]

    const int tid  = threadIdx.x;
    const int lane = tid & 31;
    const int w    = tid >> 5;
    const int la3  = lane & 3;
    const int lg4  = lane >> 2;
    const int mg   = w & 3;          // m-group (32 rows)
    const int nh   = w >> 2;         // n-half (64 cols)
    const int R    = mg * 32;

    const int bh = blockIdx.x;       // 0..15
    const int qt = blockIdx.y;       // 0..7
    const int b  = bh >> 3;
    const int h  = bh & 7;

    const float scale = 0.088388347648318447f;   // 1/sqrt(128)

    const float* Qg = g_q + (size_t)b * SEQ * DMODEL + (size_t)h * 128 * DMODEL + (size_t)qt * 128 * DV;
    const float* Kg = g_k + (size_t)b * SEQ * DV;
    const float* Vg = g_v + (size_t)b * SEQ * DV;
    float*       Og = g_o + (size_t)b * SEQ * DMODEL + (size_t)h * 128 * DMODEL + (size_t)qt * 128 * DV;

    // load Q tile (pre-scaled, tf32-rounded), float4 stores
#pragma unroll
    for (int i = 0; i < 16; i++) {
        int vid = tid + i * 256;
        int r = vid >> 5, cc = (vid & 31) * 4;
        float4 f = *(const float4*)&Qg[(size_t)r * 128 + cc];
        f.x = tf32r(f.x * scale); f.y = tf32r(f.y * scale);
        f.z = tf32r(f.z * scale); f.w = tf32r(f.w * scale);
        *(float4*)&Qs[r][cc] = f;
    }

    float oacc[2][8][4];
#pragma unroll
    for (int mt = 0; mt < 2; mt++)
#pragma unroll
        for (int nt = 0; nt < 8; nt++)
#pragma unroll
            for (int i = 0; i < 4; i++) oacc[mt][nt][i] = 0.f;
    float mM[2][2] = {{-1e30f, -1e30f}, {-1e30f, -1e30f}};
    float lS[2][2] = {{0.f, 0.f}, {0.f, 0.f}};

    for (int j = 0; j < 8; j++) {
        __syncthreads();    // prior iter's P/V reads done (and Q visible on j==0)
        // K tile: own commit group (waited first)
#pragma unroll
        for (int i = 0; i < 16; i++) {
            int vid = tid + i * 256;
            int r = vid >> 5, cc = (vid & 31) * 4;
            cpa16(&Ks[r][cc], &Kg[(size_t)(j * 128 + r) * 128 + cc]);
        }
        asm volatile("cp.async.commit_group;\n" ::: "memory");
        // V tile: second commit group (waited after GEMM1)
#pragma unroll
        for (int i = 0; i < 16; i++) {
            int vid = tid + i * 256;
            int r = vid >> 5, cc = (vid & 31) * 4;
            cpa16(&Vs[r][cc], &Vg[(size_t)(j * 128 + r) * 128 + cc]);
        }
        asm volatile("cp.async.commit_group;\n" ::: "memory");
        asm volatile("cp.async.wait_group 1;\n" ::: "memory");   // K arrived
        __syncthreads();

        // GEMM1: S[R..R+32][nh*64..+64] = Q @ K^T   (V load in flight)
        float s[2][8][4];
#pragma unroll
        for (int mt = 0; mt < 2; mt++)
#pragma unroll
            for (int nt = 0; nt < 8; nt++)
#pragma unroll
                for (int i = 0; i < 4; i++) s[mt][nt][i] = 0.f;

#pragma unroll
        for (int kk = 0; kk < 16; kk++) {
            const int k0 = kk * 8;
            unsigned a[2][4];
#pragma unroll
            for (int mt = 0; mt < 2; mt++) {
                int r = R + mt * 16 + lg4;
                a[mt][0] = __float_as_uint(Qs[r][k0 + la3]);
                a[mt][1] = __float_as_uint(Qs[r + 8][k0 + la3]);
                a[mt][2] = __float_as_uint(Qs[r][k0 + la3 + 4]);
                a[mt][3] = __float_as_uint(Qs[r + 8][k0 + la3 + 4]);
            }
#pragma unroll
            for (int nt = 0; nt < 8; nt++) {
                int cn = nh * 64 + nt * 8 + lg4;
                unsigned bb[2];
                bb[0] = __float_as_uint(Ks[cn][k0 + la3]);
                bb[1] = __float_as_uint(Ks[cn][k0 + la3 + 4]);
                mma_tf32(s[0][nt], a[0], bb);
                mma_tf32(s[1][nt], a[1], bb);
            }
        }

        // V must be complete before any thread reads Vs in GEMM2; the redM
        // __syncthreads below provides the cross-thread barrier after this wait.
        asm volatile("cp.async.wait_group 0;\n" ::: "memory");

        // ---- softmax: local (64-col) max, quad reduce, exchange with partner warp ----
        float rm[2][2] = {{-1e30f, -1e30f}, {-1e30f, -1e30f}};
#pragma unroll
        for (int mt = 0; mt < 2; mt++)
#pragma unroll
            for (int nt = 0; nt < 8; nt++) {
                rm[mt][0] = fmaxf(rm[mt][0], fmaxf(s[mt][nt][0], s[mt][nt][1]));
                rm[mt][1] = fmaxf(rm[mt][1], fmaxf(s[mt][nt][2], s[mt][nt][3]));
            }
#pragma unroll
        for (int mt = 0; mt < 2; mt++)
#pragma unroll
            for (int hh = 0; hh < 2; hh++) {
                rm[mt][hh] = fmaxf(rm[mt][hh], __shfl_xor_sync(0xffffffffu, rm[mt][hh], 1));
                rm[mt][hh] = fmaxf(rm[mt][hh], __shfl_xor_sync(0xffffffffu, rm[mt][hh], 2));
            }
        if (la3 == 0) {
#pragma unroll
            for (int mt = 0; mt < 2; mt++)
#pragma unroll
                for (int hh = 0; hh < 2; hh++)
                    redM[nh * 128 + R + mt * 16 + hh * 8 + lg4] = rm[mt][hh];
        }
        __syncthreads();   // GEMM1 Ks reads done; V visible to all threads

        float al[2][2];
#pragma unroll
        for (int mt = 0; mt < 2; mt++)
#pragma unroll
            for (int hh = 0; hh < 2; hh++) {
                float other = redM[(nh ^ 1) * 128 + R + mt * 16 + hh * 8 + lg4];
                float mnew  = fmaxf(mM[mt][hh], fmaxf(rm[mt][hh], other));
                al[mt][hh]  = __expf(mM[mt][hh] - mnew);
                mM[mt][hh]  = mnew;
            }

        float rs[2][2] = {{0.f, 0.f}, {0.f, 0.f}};
#pragma unroll
        for (int mt = 0; mt < 2; mt++)
#pragma unroll
            for (int nt = 0; nt < 8; nt++) {
                s[mt][nt][0] = __expf(s[mt][nt][0] - mM[mt][0]);
                s[mt][nt][1] = __expf(s[mt][nt][1] - mM[mt][0]);
                s[mt][nt][2] = __expf(s[mt][nt][2] - mM[mt][1]);
                s[mt][nt][3] = __expf(s[mt][nt][3] - mM[mt][1]);
                rs[mt][0] += s[mt][nt][0] + s[mt][nt][1];
                rs[mt][1] += s[mt][nt][2] + s[mt][nt][3];
            }
#pragma unroll
        for (int mt = 0; mt < 2; mt++)
#pragma unroll
            for (int hh = 0; hh < 2; hh++) {
                rs[mt][hh] += __shfl_xor_sync(0xffffffffu, rs[mt][hh], 1);
                rs[mt][hh] += __shfl_xor_sync(0xffffffffu, rs[mt][hh], 2);
            }
        if (la3 == 0) {
#pragma unroll
            for (int mt = 0; mt < 2; mt++)
#pragma unroll
                for (int hh = 0; hh < 2; hh++)
                    redS[nh * 128 + R + mt * 16 + hh * 8 + lg4] = rs[mt][hh];
        }
        __syncthreads();

#pragma unroll
        for (int mt = 0; mt < 2; mt++)
#pragma unroll
            for (int hh = 0; hh < 2; hh++) {
                float other = redS[(nh ^ 1) * 128 + R + mt * 16 + hh * 8 + lg4];
                lS[mt][hh] = lS[mt][hh] * al[mt][hh] + rs[mt][hh] + other;
            }
#pragma unroll
        for (int mt = 0; mt < 2; mt++)
#pragma unroll
            for (int nt = 0; nt < 8; nt++) {
                oacc[mt][nt][0] *= al[mt][0];
                oacc[mt][nt][1] *= al[mt][0];
                oacc[mt][nt][2] *= al[mt][1];
                oacc[mt][nt][3] *= al[mt][1];
            }

        // write P into Ks buffer (tf32-rounded), float2 stores
#pragma unroll
        for (int mt = 0; mt < 2; mt++)
#pragma unroll
            for (int nt = 0; nt < 8; nt++) {
                int r  = R + mt * 16 + lg4;
                int pc = nh * 64 + nt * 8 + la3 * 2;
                *(float2*)&Ks[r][pc]     = make_float2(tf32r(s[mt][nt][0]), tf32r(s[mt][nt][1]));
                *(float2*)&Ks[r + 8][pc] = make_float2(tf32r(s[mt][nt][2]), tf32r(s[mt][nt][3]));
            }
        __syncthreads();

        // GEMM2: O[R..+32][nh*64..+64] += P[R..+32][0..128] @ V[0..128][nh*64..+64]
#pragma unroll
        for (int kk = 0; kk < 16; kk++) {
            const int k0 = kk * 8;
            unsigned a[2][4];
#pragma unroll
            for (int mt = 0; mt < 2; mt++) {
                int r = R + mt * 16 + lg4;
                a[mt][0] = __float_as_uint(Ks[r][k0 + la3]);
                a[mt][1] = __float_as_uint(Ks[r + 8][k0 + la3]);
                a[mt][2] = __float_as_uint(Ks[r][k0 + la3 + 4]);
                a[mt][3] = __float_as_uint(Ks[r + 8][k0 + la3 + 4]);
            }
#pragma unroll
            for (int nt = 0; nt < 8; nt++) {
                int cn = nh * 64 + nt * 8 + lg4;
                unsigned bb[2];
                bb[0] = __float_as_uint(Vs[k0 + la3][cn]);
                bb[1] = __float_as_uint(Vs[k0 + la3 + 4][cn]);
                mma_tf32(oacc[0][nt], a[0], bb);
                mma_tf32(oacc[1][nt], a[1], bb);
            }
        }
    }

    // epilogue: divide by denom, tf32-round (feeds Wo GEMM directly), write
    float inv[2][2];
#pragma unroll
    for (int mt = 0; mt < 2; mt++) {
        inv[mt][0] = 1.f / lS[mt][0];
        inv[mt][1] = 1.f / lS[mt][1];
    }
#pragma unroll
    for (int mt = 0; mt < 2; mt++)
#pragma unroll
        for (int nt = 0; nt < 8; nt++) {
            int r  = R + mt * 16 + lg4;
            int cc = nh * 64 + nt * 8 + la3 * 2;
            *(float2*)&Og[(size_t)r * 128 + cc] =
                make_float2(tf32r(oacc[mt][nt][0] * inv[mt][0]),
                            tf32r(oacc[mt][nt][1] * inv[mt][0]));
            *(float2*)&Og[(size_t)(r + 8) * 128 + cc] =
                make_float2(tf32r(oacc[mt][nt][2] * inv[mt][1]),
                            tf32r(oacc[mt][nt][3] * inv[mt][1]));
        }
}

// ---------------------------------------------------------------------------
extern "C" void kernel_launch(void* const* d_in, const int* in_sizes, int n_in,
                              void* d_out, int out_size)
{
    const float* x  = (const float*)d_in[0];
    const float* Wq = (const float*)d_in[1];
    const float* bq = (const float*)d_in[2];
    const float* Wk = (const float*)d_in[3];
    const float* bk = (const float*)d_in[4];
    const float* Wv = (const float*)d_in[5];
    const float* bv = (const float*)d_in[6];
    const float* Wo = (const float*)d_in[7];
    const float* bo = (const float*)d_in[8];
    float* out = (float*)d_out;

    const int GEMM_SMEM = (2 * 128 * 36 + 2 * 32 * 72) * 4;                  // 55296 B
    const int ATTN_SMEM = (2 * 128 * 132 + 128 * 136 + 512) * 4;             // 206848 B
    cudaFuncSetAttribute(qkv_kernel,  cudaFuncAttributeMaxDynamicSharedMemorySize, GEMM_SMEM);
    cudaFuncSetAttribute(wo_kernel,   cudaFuncAttributeMaxDynamicSharedMemorySize, GEMM_SMEM);
    cudaFuncSetAttribute(attn_kernel, cudaFuncAttributeMaxDynamicSharedMemorySize, ATTN_SMEM);

    // 1. round all inputs to tf32 once
    round_pre<<<512, 256>>>(x, Wq, Wk, Wv, Wo);
    // 2. fused Q|K|V projections (320 CTAs, 2/SM)
    qkv_kernel<<<dim3(20, 16), 256, GEMM_SMEM>>>(bq, bk, bv);
    // 3. attention (128 CTAs)
    attn_kernel<<<dim3(16, 8), 256, ATTN_SMEM>>>();
    // 4. output projection (256 CTAs, 2/SM)
    wo_kernel<<<dim3(16, 16), 256, GEMM_SMEM>>>(bo, out);
}

// round 12
// speedup vs baseline: 1.4948x; 1.0118x over previous
#include <cuda_runtime.h>

#define SEQ    1024
#define DMODEL 1024
#define DV     128

// ------------------------- scratch (__device__ globals) ---------------------
__device__ float g_xr [2 * SEQ * DMODEL];     // tf32-rounded x
__device__ float g_wqr[DMODEL * DMODEL];
__device__ float g_wkr[DMODEL * DV];
__device__ float g_wvr[DMODEL * DV];
__device__ float g_wor[DMODEL * DMODEL];
__device__ float g_q  [2 * SEQ * DMODEL];
__device__ float g_k  [2 * SEQ * DV];     // tf32-rounded by producer
__device__ float g_v  [2 * SEQ * DV];     // tf32-rounded by producer
__device__ float g_o  [2 * SEQ * DMODEL]; // tf32-rounded by attn epilogue

// round-to-nearest tf32
__device__ __forceinline__ float tf32r(float x) {
    asm("cvt.rna.tf32.f32 %0, %0;" : "+f"(x));
    return x;
}

__device__ __forceinline__ void mma_tf32(float c[4], const unsigned a[4], const unsigned b[2]) {
    asm volatile(
        "mma.sync.aligned.m16n8k8.row.col.f32.tf32.tf32.f32 "
        "{%0,%1,%2,%3}, {%4,%5,%6,%7}, {%8,%9}, {%0,%1,%2,%3};\n"
        : "+f"(c[0]), "+f"(c[1]), "+f"(c[2]), "+f"(c[3])
        : "r"(a[0]), "r"(a[1]), "r"(a[2]), "r"(a[3]), "r"(b[0]), "r"(b[1]));
}

// ------------------------- prepass: round inputs to tf32 --------------------
__global__ void round_pre(const float* __restrict__ x,  const float* __restrict__ wq,
                          const float* __restrict__ wk, const float* __restrict__ wv,
                          const float* __restrict__ wo)
{
    const size_t E0 = 524288;            // x      float4 count
    const size_t E1 = E0 + 262144;       // wq
    const size_t E2 = E1 + 32768;        // wk
    const size_t E3 = E2 + 32768;        // wv
    const size_t E4 = E3 + 262144;       // wo
    size_t i = (size_t)blockIdx.x * blockDim.x + threadIdx.x;
    size_t stride = (size_t)gridDim.x * blockDim.x;
    for (; i < E4; i += stride) {
        const float4* s; float4* d; size_t off;
        if      (i < E0) { s = (const float4*)x;  d = (float4*)g_xr;  off = i;      }
        else if (i < E1) { s = (const float4*)wq; d = (float4*)g_wqr; off = i - E0; }
        else if (i < E2) { s = (const float4*)wk; d = (float4*)g_wkr; off = i - E1; }
        else if (i < E3) { s = (const float4*)wv; d = (float4*)g_wvr; off = i - E2; }
        else             { s = (const float4*)wo; d = (float4*)g_wor; off = i - E3; }
        float4 f = s[off];
        f.x = tf32r(f.x); f.y = tf32r(f.y); f.z = tf32r(f.z); f.w = tf32r(f.w);
        d[off] = f;
    }
}

// ------------------------- GEMM core (BM=128 BN=128 BK=32) ------------------
// R5-proven geometry: 256 threads / 8 warps, warp tile 64x32 (best measured
// ILP per fragment-load). 3-stage cp.async pipeline with wait_group 1 —
// loads run 2 iterations ahead, hiding the 577-cyc DRAM latency that bound R5.
// smem: 3 x (As 128x36 + Bs 32x136) x4B = 107520 B (x2 CTAs = 215 KB < 228 KB).

__device__ __forceinline__ void cpa16(float* dst, const float* src) {
    unsigned d = (unsigned)__cvta_generic_to_shared(dst);
    asm volatile("cp.async.cg.shared.global [%0], [%1], 16;\n" :: "r"(d), "l"(src) : "memory");
}

#define AS_STAGE (128 * 36)
#define BS_STAGE (32 * 136)
#define BS_BASE  (3 * AS_STAGE)

__device__ __forceinline__ void gemm_load_tiles(float* sm, int s,
                                                const float* __restrict__ A,
                                                const float* __restrict__ Bm,
                                                int N, int bm, int bn, int kb, int tid)
{
    float* As = sm + s * AS_STAGE;
    float* Bs = sm + BS_BASE + s * BS_STAGE;
#pragma unroll
    for (int i = 0; i < 4; i++) {                 // A: 128x32 -> 1024 16B chunks
        int id = tid + i * 256;
        int r = id >> 3, c4 = (id & 7) * 4;
        cpa16(As + r * 36 + c4, A + (size_t)(bm + r) * 1024 + kb + c4);
    }
#pragma unroll
    for (int i = 0; i < 4; i++) {                 // B: 32x128 -> 1024 16B chunks
        int id = tid + i * 256;
        int r = id >> 5, c4 = (id & 31) * 4;
        cpa16(Bs + r * 136 + c4, Bm + (size_t)(kb + r) * N + bn + c4);
    }
    asm volatile("cp.async.commit_group;\n" ::: "memory");
}

__device__ __forceinline__ void gemm_core(const float* __restrict__ A,
                                          const float* __restrict__ Bm,
                                          const float* __restrict__ bias,
                                          float* __restrict__ C,
                                          int N, int Nc, int bm, int bn, int bnc,
                                          float* sm, bool ROUND)
{
    const int tid  = threadIdx.x;
    const int lane = tid & 31;
    const int w    = tid >> 5;
    const int la3  = lane & 3;
    const int lg4  = lane >> 2;
    const int wm   = (w & 1) * 64;       // 2 m-groups (64 rows)
    const int wn   = (w >> 1) * 32;      // 4 n-groups (32 cols)

    float c[4][4][4];
#pragma unroll
    for (int mt = 0; mt < 4; mt++)
#pragma unroll
        for (int nt = 0; nt < 4; nt++)
#pragma unroll
            for (int i = 0; i < 4; i++) c[mt][nt][i] = 0.f;

    // prologue: stages 0 and 1 in flight
    gemm_load_tiles(sm, 0, A, Bm, N, bm, bn, 0, tid);
    gemm_load_tiles(sm, 1, A, Bm, N, bm, bn, 32, tid);

    for (int kbi = 0; kbi < 32; kbi++) {
        const int s = kbi % 3;
        if (kbi < 31)
            asm volatile("cp.async.wait_group 1;\n" ::: "memory");   // group kbi done
        else
            asm volatile("cp.async.wait_group 0;\n" ::: "memory");   // last group done
        __syncthreads();     // stage s ready; all warps finished stage s (prev use)
        if (kbi < 30)
            gemm_load_tiles(sm, (kbi + 2) % 3, A, Bm, N, bm, bn, (kbi + 2) * 32, tid);

        float (*As)[36]  = (float(*)[36])(sm + s * AS_STAGE);
        float (*Bs)[136] = (float(*)[136])(sm + BS_BASE + s * BS_STAGE);
#pragma unroll
        for (int kk = 0; kk < 4; kk++) {
            const int k0 = kk * 8;
            unsigned a[4][4];
#pragma unroll
            for (int mt = 0; mt < 4; mt++) {
                int r = wm + mt * 16 + lg4;
                a[mt][0] = __float_as_uint(As[r][k0 + la3]);
                a[mt][1] = __float_as_uint(As[r + 8][k0 + la3]);
                a[mt][2] = __float_as_uint(As[r][k0 + la3 + 4]);
                a[mt][3] = __float_as_uint(As[r + 8][k0 + la3 + 4]);
            }
            unsigned b[4][2];
#pragma unroll
            for (int nt = 0; nt < 4; nt++) {
                int cn = wn + nt * 8 + lg4;
                b[nt][0] = __float_as_uint(Bs[k0 + la3][cn]);
                b[nt][1] = __float_as_uint(Bs[k0 + la3 + 4][cn]);
            }
#pragma unroll
            for (int mt = 0; mt < 4; mt++)
#pragma unroll
                for (int nt = 0; nt < 4; nt++)
                    mma_tf32(c[mt][nt], a[mt], b[nt]);
        }
    }

    // epilogue: +bias (optionally tf32-rounded for downstream mma consumers)
#pragma unroll
    for (int mt = 0; mt < 4; mt++) {
#pragma unroll
        for (int nt = 0; nt < 4; nt++) {
            int row = bm + wm + mt * 16 + lg4;
            int cn  = wn + nt * 8 + la3 * 2;
            float b0 = bias[bn + cn], b1 = bias[bn + cn + 1];
            float v00 = c[mt][nt][0] + b0, v01 = c[mt][nt][1] + b1;
            float v10 = c[mt][nt][2] + b0, v11 = c[mt][nt][3] + b1;
            if (ROUND) { v00 = tf32r(v00); v01 = tf32r(v01); v10 = tf32r(v10); v11 = tf32r(v11); }
            *(float2*)&C[(size_t)row * Nc + bnc + cn]       = make_float2(v00, v01);
            *(float2*)&C[(size_t)(row + 8) * Nc + bnc + cn] = make_float2(v10, v11);
        }
    }
}

// Fused QKV projection: grid (10, 16). bx<8 -> Q col-block, bx==8 -> K, bx==9 -> V.
__global__ __launch_bounds__(256, 2)
void qkv_kernel(const float* __restrict__ bq, const float* __restrict__ bk,
                const float* __restrict__ bv)
{
    extern __shared__ float sm[];
    const int bx = blockIdx.x;
    const int bm = blockIdx.y * 128;
    if (bx < 8)
        gemm_core(g_xr, g_wqr, bq, g_q, 1024, 1024, bm, bx * 128, bx * 128, sm, false);
    else if (bx == 8)
        gemm_core(g_xr, g_wkr, bk, g_k, 128, 128, bm, 0, 0, sm, true);
    else
        gemm_core(g_xr, g_wvr, bv, g_v, 128, 128, bm, 0, 0, sm, true);
}

// Output projection: grid (8, 16).
__global__ __launch_bounds__(256, 2)
void wo_kernel(const float* __restrict__ bo, float* __restrict__ out)
{
    extern __shared__ float sm[];
    gemm_core(g_o, g_wor, bo, out, 1024, 1024, blockIdx.y * 128, blockIdx.x * 128,
              blockIdx.x * 128, sm, false);
}

// ------------------------- fused flash attention ----------------------------
// Unchanged from R10 (measured improvement; hold it).
// CTA: one (b,h,qtile) = 128 queries x 1024 keys. 8 warps = 4 m-groups x 2 n-halves;
// warp tile 32 rows x 64 key cols. Cross-warp softmax via redM/redS smem exchange.
// K/V tf32-rounded by producer -> pure cp.async copies; split-wait hides V load
// behind GEMM1. smem: Qs[128][132] Ks[128][132](P) Vs[128][136] red[512] = 206848 B.
__global__ __launch_bounds__(256)
void attn_kernel()
{
    extern __shared__ float sm[];
    float (*Qs)[132] = (float(*)[132])sm;
    float (*Ks)[132] = (float(*)[132])(sm + 128 * 132);
    float (*Vs)[136] = (float(*)[136])(sm + 2 * 128 * 132);
    float* redM = sm + 2 * 128 * 132 + 128 * 136;   // [2][128]
    float* redS = redM + 256;                        // [2][128]

    const int tid  = threadIdx.x;
    const int lane = tid & 31;
    const int w    = tid >> 5;
    const int la3  = lane & 3;
    const int lg4  = lane >> 2;
    const int mg   = w & 3;          // m-group (32 rows)
    const int nh   = w >> 2;         // n-half (64 cols)
    const int R    = mg * 32;

    const int bh = blockIdx.x;       // 0..15
    const int qt = blockIdx.y;       // 0..7
    const int b  = bh >> 3;
    const int h  = bh & 7;

    const float scale = 0.088388347648318447f;   // 1/sqrt(128)

    const float* Qg = g_q + (size_t)b * SEQ * DMODEL + (size_t)h * 128 * DMODEL + (size_t)qt * 128 * DV;
    const float* Kg = g_k + (size_t)b * SEQ * DV;
    const float* Vg = g_v + (size_t)b * SEQ * DV;
    float*       Og = g_o + (size_t)b * SEQ * DMODEL + (size_t)h * 128 * DMODEL + (size_t)qt * 128 * DV;

    // load Q tile (pre-scaled, tf32-rounded), float4 stores
#pragma unroll
    for (int i = 0; i < 16; i++) {
        int vid = tid + i * 256;
        int r = vid >> 5, cc = (vid & 31) * 4;
        float4 f = *(const float4*)&Qg[(size_t)r * 128 + cc];
        f.x = tf32r(f.x * scale); f.y = tf32r(f.y * scale);
        f.z = tf32r(f.z * scale); f.w = tf32r(f.w * scale);
        *(float4*)&Qs[r][cc] = f;
    }

    float oacc[2][8][4];
#pragma unroll
    for (int mt = 0; mt < 2; mt++)
#pragma unroll
        for (int nt = 0; nt < 8; nt++)
#pragma unroll
            for (int i = 0; i < 4; i++) oacc[mt][nt][i] = 0.f;
    float mM[2][2] = {{-1e30f, -1e30f}, {-1e30f, -1e30f}};
    float lS[2][2] = {{0.f, 0.f}, {0.f, 0.f}};

    for (int j = 0; j < 8; j++) {
        __syncthreads();    // prior iter's P/V reads done (and Q visible on j==0)
        // K tile: own commit group (waited first)
#pragma unroll
        for (int i = 0; i < 16; i++) {
            int vid = tid + i * 256;
            int r = vid >> 5, cc = (vid & 31) * 4;
            cpa16(&Ks[r][cc], &Kg[(size_t)(j * 128 + r) * 128 + cc]);
        }
        asm volatile("cp.async.commit_group;\n" ::: "memory");
        // V tile: second commit group (waited after GEMM1)
#pragma unroll
        for (int i = 0; i < 16; i++) {
            int vid = tid + i * 256;
            int r = vid >> 5, cc = (vid & 31) * 4;
            cpa16(&Vs[r][cc], &Vg[(size_t)(j * 128 + r) * 128 + cc]);
        }
        asm volatile("cp.async.commit_group;\n" ::: "memory");
        asm volatile("cp.async.wait_group 1;\n" ::: "memory");   // K arrived
        __syncthreads();

        // GEMM1: S[R..R+32][nh*64..+64] = Q @ K^T   (V load in flight)
        float s[2][8][4];
#pragma unroll
        for (int mt = 0; mt < 2; mt++)
#pragma unroll
            for (int nt = 0; nt < 8; nt++)
#pragma unroll
                for (int i = 0; i < 4; i++) s[mt][nt][i] = 0.f;

#pragma unroll
        for (int kk = 0; kk < 16; kk++) {
            const int k0 = kk * 8;
            unsigned a[2][4];
#pragma unroll
            for (int mt = 0; mt < 2; mt++) {
                int r = R + mt * 16 + lg4;
                a[mt][0] = __float_as_uint(Qs[r][k0 + la3]);
                a[mt][1] = __float_as_uint(Qs[r + 8][k0 + la3]);
                a[mt][2] = __float_as_uint(Qs[r][k0 + la3 + 4]);
                a[mt][3] = __float_as_uint(Qs[r + 8][k0 + la3 + 4]);
            }
#pragma unroll
            for (int nt = 0; nt < 8; nt++) {
                int cn = nh * 64 + nt * 8 + lg4;
                unsigned bb[2];
                bb[0] = __float_as_uint(Ks[cn][k0 + la3]);
                bb[1] = __float_as_uint(Ks[cn][k0 + la3 + 4]);
                mma_tf32(s[0][nt], a[0], bb);
                mma_tf32(s[1][nt], a[1], bb);
            }
        }

        // V must be complete before any thread reads Vs in GEMM2; the redM
        // __syncthreads below provides the cross-thread barrier after this wait.
        asm volatile("cp.async.wait_group 0;\n" ::: "memory");

        // ---- softmax: local (64-col) max, quad reduce, exchange with partner warp ----
        float rm[2][2] = {{-1e30f, -1e30f}, {-1e30f, -1e30f}};
#pragma unroll
        for (int mt = 0; mt < 2; mt++)
#pragma unroll
            for (int nt = 0; nt < 8; nt++) {
                rm[mt][0] = fmaxf(rm[mt][0], fmaxf(s[mt][nt][0], s[mt][nt][1]));
                rm[mt][1] = fmaxf(rm[mt][1], fmaxf(s[mt][nt][2], s[mt][nt][3]));
            }
#pragma unroll
        for (int mt = 0; mt < 2; mt++)
#pragma unroll
            for (int hh = 0; hh < 2; hh++) {
                rm[mt][hh] = fmaxf(rm[mt][hh], __shfl_xor_sync(0xffffffffu, rm[mt][hh], 1));
                rm[mt][hh] = fmaxf(rm[mt][hh], __shfl_xor_sync(0xffffffffu, rm[mt][hh], 2));
            }
        if (la3 == 0) {
#pragma unroll
            for (int mt = 0; mt < 2; mt++)
#pragma unroll
                for (int hh = 0; hh < 2; hh++)
                    redM[nh * 128 + R + mt * 16 + hh * 8 + lg4] = rm[mt][hh];
        }
        __syncthreads();   // GEMM1 Ks reads done; V visible to all threads

        float al[2][2];
#pragma unroll
        for (int mt = 0; mt < 2; mt++)
#pragma unroll
            for (int hh = 0; hh < 2; hh++) {
                float other = redM[(nh ^ 1) * 128 + R + mt * 16 + hh * 8 + lg4];
                float mnew  = fmaxf(mM[mt][hh], fmaxf(rm[mt][hh], other));
                al[mt][hh]  = __expf(mM[mt][hh] - mnew);
                mM[mt][hh]  = mnew;
            }

        float rs[2][2] = {{0.f, 0.f}, {0.f, 0.f}};
#pragma unroll
        for (int mt = 0; mt < 2; mt++)
#pragma unroll
            for (int nt = 0; nt < 8; nt++) {
                s[mt][nt][0] = __expf(s[mt][nt][0] - mM[mt][0]);
                s[mt][nt][1] = __expf(s[mt][nt][1] - mM[mt][0]);
                s[mt][nt][2] = __expf(s[mt][nt][2] - mM[mt][1]);
                s[mt][nt][3] = __expf(s[mt][nt][3] - mM[mt][1]);
                rs[mt][0] += s[mt][nt][0] + s[mt][nt][1];
                rs[mt][1] += s[mt][nt][2] + s[mt][nt][3];
            }
#pragma unroll
        for (int mt = 0; mt < 2; mt++)
#pragma unroll
            for (int hh = 0; hh < 2; hh++) {
                rs[mt][hh] += __shfl_xor_sync(0xffffffffu, rs[mt][hh], 1);
                rs[mt][hh] += __shfl_xor_sync(0xffffffffu, rs[mt][hh], 2);
            }
        if (la3 == 0) {
#pragma unroll
            for (int mt = 0; mt < 2; mt++)
#pragma unroll
                for (int hh = 0; hh < 2; hh++)
                    redS[nh * 128 + R + mt * 16 + hh * 8 + lg4] = rs[mt][hh];
        }
        __syncthreads();

#pragma unroll
        for (int mt = 0; mt < 2; mt++)
#pragma unroll
            for (int hh = 0; hh < 2; hh++) {
                float other = redS[(nh ^ 1) * 128 + R + mt * 16 + hh * 8 + lg4];
                lS[mt][hh] = lS[mt][hh] * al[mt][hh] + rs[mt][hh] + other;
            }
#pragma unroll
        for (int mt = 0; mt < 2; mt++)
#pragma unroll
            for (int nt = 0; nt < 8; nt++) {
                oacc[mt][nt][0] *= al[mt][0];
                oacc[mt][nt][1] *= al[mt][0];
                oacc[mt][nt][2] *= al[mt][1];
                oacc[mt][nt][3] *= al[mt][1];
            }

        // write P into Ks buffer (tf32-rounded), float2 stores
#pragma unroll
        for (int mt = 0; mt < 2; mt++)
#pragma unroll
            for (int nt = 0; nt < 8; nt++) {
                int r  = R + mt * 16 + lg4;
                int pc = nh * 64 + nt * 8 + la3 * 2;
                *(float2*)&Ks[r][pc]     = make_float2(tf32r(s[mt][nt][0]), tf32r(s[mt][nt][1]));
                *(float2*)&Ks[r + 8][pc] = make_float2(tf32r(s[mt][nt][2]), tf32r(s[mt][nt][3]));
            }
        __syncthreads();

        // GEMM2: O[R..+32][nh*64..+64] += P[R..+32][0..128] @ V[0..128][nh*64..+64]
#pragma unroll
        for (int kk = 0; kk < 16; kk++) {
            const int k0 = kk * 8;
            unsigned a[2][4];
#pragma unroll
            for (int mt = 0; mt < 2; mt++) {
                int r = R + mt * 16 + lg4;
                a[mt][0] = __float_as_uint(Ks[r][k0 + la3]);
                a[mt][1] = __float_as_uint(Ks[r + 8][k0 + la3]);
                a[mt][2] = __float_as_uint(Ks[r][k0 + la3 + 4]);
                a[mt][3] = __float_as_uint(Ks[r + 8][k0 + la3 + 4]);
            }
#pragma unroll
            for (int nt = 0; nt < 8; nt++) {
                int cn = nh * 64 + nt * 8 + lg4;
                unsigned bb[2];
                bb[0] = __float_as_uint(Vs[k0 + la3][cn]);
                bb[1] = __float_as_uint(Vs[k0 + la3 + 4][cn]);
                mma_tf32(oacc[0][nt], a[0], bb);
                mma_tf32(oacc[1][nt], a[1], bb);
            }
        }
    }

    // epilogue: divide by denom, tf32-round (feeds Wo GEMM directly), write
    float inv[2][2];
#pragma unroll
    for (int mt = 0; mt < 2; mt++) {
        inv[mt][0] = 1.f / lS[mt][0];
        inv[mt][1] = 1.f / lS[mt][1];
    }
#pragma unroll
    for (int mt = 0; mt < 2; mt++)
#pragma unroll
        for (int nt = 0; nt < 8; nt++) {
            int r  = R + mt * 16 + lg4;
            int cc = nh * 64 + nt * 8 + la3 * 2;
            *(float2*)&Og[(size_t)r * 128 + cc] =
                make_float2(tf32r(oacc[mt][nt][0] * inv[mt][0]),
                            tf32r(oacc[mt][nt][1] * inv[mt][0]));
            *(float2*)&Og[(size_t)(r + 8) * 128 + cc] =
                make_float2(tf32r(oacc[mt][nt][2] * inv[mt][1]),
                            tf32r(oacc[mt][nt][3] * inv[mt][1]));
        }
}

// ---------------------------------------------------------------------------
extern "C" void kernel_launch(void* const* d_in, const int* in_sizes, int n_in,
                              void* d_out, int out_size)
{
    const float* x  = (const float*)d_in[0];
    const float* Wq = (const float*)d_in[1];
    const float* bq = (const float*)d_in[2];
    const float* Wk = (const float*)d_in[3];
    const float* bk = (const float*)d_in[4];
    const float* Wv = (const float*)d_in[5];
    const float* bv = (const float*)d_in[6];
    const float* Wo = (const float*)d_in[7];
    const float* bo = (const float*)d_in[8];
    float* out = (float*)d_out;

    const int GEMM_SMEM = 3 * (AS_STAGE + BS_STAGE) * 4;                     // 107520 B
    const int ATTN_SMEM = (2 * 128 * 132 + 128 * 136 + 512) * 4;             // 206848 B
    cudaFuncSetAttribute(qkv_kernel,  cudaFuncAttributeMaxDynamicSharedMemorySize, GEMM_SMEM);
    cudaFuncSetAttribute(wo_kernel,   cudaFuncAttributeMaxDynamicSharedMemorySize, GEMM_SMEM);
    cudaFuncSetAttribute(attn_kernel, cudaFuncAttributeMaxDynamicSharedMemorySize, ATTN_SMEM);

    // 1. round all inputs to tf32 once
    round_pre<<<512, 256>>>(x, Wq, Wk, Wv, Wo);
    // 2. fused Q|K|V projections (160 CTAs)
    qkv_kernel<<<dim3(10, 16), 256, GEMM_SMEM>>>(bq, bk, bv);
    // 3. attention (128 CTAs)
    attn_kernel<<<dim3(16, 8), 256, ATTN_SMEM>>>();
    // 4. output projection (128 CTAs)
    wo_kernel<<<dim3(8, 16), 256, GEMM_SMEM>>>(bo, out);
}